// round 4
// baseline (speedup 1.0000x reference)
#include <cuda_runtime.h>
#include <cuda_bf16.h>
#include <math.h>

// ---------------------------------------------------------------------------
// 512 independent diffusion chains; one persistent CTA (128 thr) per chain.
// All hot-loop math via packed fma.rn.f32x2 (full-rate Blackwell fp32).
// ---------------------------------------------------------------------------

#define NSTEPS 50
typedef unsigned long long u64;

// ---- device-global scratch (no allocations allowed) ----
__device__ float  g_loc[32 * 128];
__device__ float  g_scale[32 * 128];
__device__ float  g_cond[6 * NSTEPS * 32];   // [l][t][c]
__device__ float  g_coef[NSTEPS * 5];        // s1m, 1/sab, c0, cxt, sig
__device__ float2 w_inT2[128 * 32];          // [d][c]   dup (w,w)
__device__ float2 wdilT2[6 * 32 * 3 * 64];   // [l][c][k][o] dup
__device__ float2 woutT2[6 * 32 * 64];       // [l][c][o] dup
__device__ float2 w_o1T2[32 * 32];           // [c][o] dup, pre-scaled 1/sqrt(6)
__device__ float2 w_o2T2[32 * 128];          // [c][d] dup

// ---- packed f32x2 helpers ----
__device__ __forceinline__ u64 fma2(u64 a, u64 b, u64 c) {
    u64 d; asm("fma.rn.f32x2 %0, %1, %2, %3;" : "=l"(d) : "l"(a), "l"(b), "l"(c)); return d;
}
__device__ __forceinline__ u64 add2(u64 a, u64 b) {
    u64 d; asm("add.rn.f32x2 %0, %1, %2;" : "=l"(d) : "l"(a), "l"(b)); return d;
}
__device__ __forceinline__ u64 mul2(u64 a, u64 b) {
    u64 d; asm("mul.rn.f32x2 %0, %1, %2;" : "=l"(d) : "l"(a), "l"(b)); return d;
}
__device__ __forceinline__ u64 pack2(float lo, float hi) {
    u64 r; asm("mov.b64 %0, {%1, %2};" : "=l"(r) : "f"(lo), "f"(hi)); return r;
}
__device__ __forceinline__ float2 unpk(u64 a) {
    float2 v; asm("mov.b64 {%0, %1}, %2;" : "=f"(v.x), "=f"(v.y) : "l"(a)); return v;
}
__device__ __forceinline__ float sigm_f(float x) { return 1.0f / (1.0f + __expf(-x)); }
__device__ __forceinline__ float tanh_f(float x) { return 1.0f - 2.0f / (__expf(2.0f * x) + 1.0f); }

// ---------------------------------------------------------------------------
// Setup: duplicated-weight transposes + DDPM schedule (double)
// ---------------------------------------------------------------------------
__global__ void k_prep(const float* __restrict__ w_in, const float* __restrict__ lwd,
                       const float* __restrict__ lwo, const float* __restrict__ w_o1,
                       const float* __restrict__ w_o2) {
    int i = blockIdx.x * blockDim.x + threadIdx.x;
    int nt = gridDim.x * blockDim.x;
    for (int idx = i; idx < 4096; idx += nt) {
        int d = idx >> 5, c = idx & 31;
        float w = w_in[c * 128 + d];
        w_inT2[idx] = make_float2(w, w);
    }
    for (int idx = i; idx < 6 * 32 * 3 * 64; idx += nt) {
        int o = idx & 63, r = idx >> 6;
        int k = r % 3, r2 = r / 3;
        int c = r2 & 31, l = r2 >> 5;
        float w = lwd[((l * 64 + o) * 32 + c) * 3 + k];
        wdilT2[idx] = make_float2(w, w);
    }
    for (int idx = i; idx < 6 * 32 * 64; idx += nt) {
        int o = idx & 63, r = idx >> 6;
        int c = r & 31, l = r >> 5;
        float w = lwo[(l * 64 + o) * 32 + c];
        woutT2[idx] = make_float2(w, w);
    }
    for (int idx = i; idx < 1024; idx += nt) {
        int o = idx & 31, c = idx >> 5;
        float w = w_o1[o * 32 + c] * 0.40824829046386302f;  // 1/sqrt(6)
        w_o1T2[idx] = make_float2(w, w);
    }
    for (int idx = i; idx < 4096; idx += nt) {
        int d = idx & 127, c = idx >> 7;
        float w = w_o2[d * 32 + c];
        w_o2T2[idx] = make_float2(w, w);
    }
    if (i == 0) {
        double abar = 1.0;
        for (int t = 0; t < NSTEPS; t++) {
            double beta = 1e-4 + (double)t * (0.1 - 1e-4) / 49.0;
            double alpha = 1.0 - beta;
            double abar_prev = abar;
            abar *= alpha;
            double om = 1.0 - abar;
            g_coef[t * 5 + 0] = (float)sqrt(om);
            g_coef[t * 5 + 1] = (float)(1.0 / sqrt(abar));
            g_coef[t * 5 + 2] = (float)(beta * sqrt(abar_prev) / om);
            g_coef[t * 5 + 3] = (float)((1.0 - abar_prev) * sqrt(alpha) / om);
            double pv = beta * (1.0 - abar_prev) / om;
            g_coef[t * 5 + 4] = (t > 0) ? (float)sqrt(pv) : 0.0f;
        }
    }
}

// ---------------------------------------------------------------------------
// Setup: EWMA Student-t marginal fit. grid 32 (b) x 128 (d)
// ---------------------------------------------------------------------------
__global__ void k_stats(const float* __restrict__ x_hist) {
    int b = blockIdx.x, d = threadIdx.x;
    const float* xb = x_hist + (size_t)b * 192 * 128 + d;
    double s = 0.0;
    for (int t = 0; t < 192; t++) s += (double)xb[t * 128];
    float mean = (float)(s / 192.0);
    float c = xb[0] - mean;
    float v = c * c;
    for (int t = 1; t < 192; t++) {
        float cc = xb[t * 128] - mean;
        v = 0.94f * v + 0.06f * (cc * cc);
    }
    g_loc[b * 128 + d] = mean;
    g_scale[b * 128 + d] = fmaxf(sqrtf(v * 0.5f), 1e-5f);
}

// ---------------------------------------------------------------------------
// Setup: step embedding + per-layer cond. grid 50 (t) x 512 threads.
// ---------------------------------------------------------------------------
__global__ void k_temb(const float* __restrict__ w1, const float* __restrict__ b1,
                       const float* __restrict__ w2, const float* __restrict__ b2,
                       const float* __restrict__ wt, const float* __restrict__ bt) {
    __shared__ float pe[128], te1[512], te2[512];
    int t = blockIdx.x, tid = threadIdx.x;
    if (tid < 64) {
        float y = ((float)tid * 4.0f) / 63.0f;
        float p = (float)pow(10.0, (double)y);
        float e = (float)t * p;
        pe[tid] = (float)sin((double)e);
        pe[tid + 64] = (float)cos((double)e);
    }
    __syncthreads();
    {
        double a = (double)b1[tid];
        for (int j = 0; j < 128; j++) a += (double)pe[j] * (double)w1[j * 512 + tid];
        te1[tid] = (float)(a / (1.0 + exp(-a)));
    }
    __syncthreads();
    {
        double a = (double)b2[tid];
        for (int k = 0; k < 512; k++) a += (double)te1[k] * (double)w2[k * 512 + tid];
        te2[tid] = (float)(a / (1.0 + exp(-a)));
    }
    __syncthreads();
    if (tid < 192) {
        int l = tid >> 5, c = tid & 31;
        double a = (double)bt[l * 32 + c];
        for (int k = 0; k < 512; k++) a += (double)te2[k] * (double)wt[(l * 512 + k) * 32 + c];
        g_cond[(l * NSTEPS + t) * 32 + c] = (float)a;
    }
}

// ---------------------------------------------------------------------------
// Dilated conv, gate+filt in one thread (o = lane, j0 = warp*6).
// ---------------------------------------------------------------------------
#define HCP_STRIDE 90

template <int DIL>
__device__ __forceinline__ void conv_pair(const float2* __restrict__ wbase,
                                          const float* hcpS, int j0,
                                          u64 ag[3], u64 af[3]) {
#pragma unroll 8
    for (int c = 0; c < 32; c++) {
        const float2* wr = wbase + c * 192;
        u64 wg0 = *(const u64*)(wr);
        u64 wf0 = *(const u64*)(wr + 32);
        u64 wg1 = *(const u64*)(wr + 64);
        u64 wf1 = *(const u64*)(wr + 96);
        u64 wg2 = *(const u64*)(wr + 128);
        u64 wf2 = *(const u64*)(wr + 160);
        const float* hp = hcpS + c * HCP_STRIDE + 32 + j0;
        if (DIL != 1) {
            u64 m[3], lv[3], rv[3];
#pragma unroll
            for (int p = 0; p < 3; p++) {
                lv[p] = *(const u64*)(hp - DIL + 2 * p);
                m[p]  = *(const u64*)(hp + 2 * p);
                rv[p] = *(const u64*)(hp + DIL + 2 * p);
            }
#pragma unroll
            for (int p = 0; p < 3; p++) {
                ag[p] = fma2(wg0, lv[p], ag[p]);
                ag[p] = fma2(wg1, m[p],  ag[p]);
                ag[p] = fma2(wg2, rv[p], ag[p]);
                af[p] = fma2(wf0, lv[p], af[p]);
                af[p] = fma2(wf1, m[p],  af[p]);
                af[p] = fma2(wf2, rv[p], af[p]);
            }
        } else {
            float v0 = hp[-1], v1 = hp[0], v2 = hp[1], v3 = hp[2];
            float v4 = hp[3], v5 = hp[4], v6 = hp[5], v7 = hp[6];
            u64 p01 = pack2(v0, v1), p12 = pack2(v1, v2), p23 = pack2(v2, v3);
            u64 p34 = pack2(v3, v4), p45 = pack2(v4, v5), p56 = pack2(v5, v6);
            u64 p67 = pack2(v6, v7);
            ag[0] = fma2(wg0, p01, ag[0]); ag[0] = fma2(wg1, p12, ag[0]); ag[0] = fma2(wg2, p23, ag[0]);
            ag[1] = fma2(wg0, p23, ag[1]); ag[1] = fma2(wg1, p34, ag[1]); ag[1] = fma2(wg2, p45, ag[1]);
            ag[2] = fma2(wg0, p45, ag[2]); ag[2] = fma2(wg1, p56, ag[2]); ag[2] = fma2(wg2, p67, ag[2]);
            af[0] = fma2(wf0, p01, af[0]); af[0] = fma2(wf1, p12, af[0]); af[0] = fma2(wf2, p23, af[0]);
            af[1] = fma2(wf0, p23, af[1]); af[1] = fma2(wf1, p34, af[1]); af[1] = fma2(wf2, p45, af[1]);
            af[2] = fma2(wf0, p45, af[2]); af[2] = fma2(wf1, p56, af[2]); af[2] = fma2(wf2, p67, af[2]);
        }
    }
}

// ---------------------------------------------------------------------------
// Main persistent kernel: grid 512 (chain) x 128 threads.
// ---------------------------------------------------------------------------
__global__ __launch_bounds__(128, 4) void k_main(
    const float* __restrict__ z_init, const float* __restrict__ noise,
    const float* __restrict__ b_in, const float* __restrict__ bdil,
    const float* __restrict__ bout, const float* __restrict__ b_o1,
    const float* __restrict__ b_o2, float* __restrict__ out) {
    __shared__ __align__(16) float xs[128 * 26];          // x state [d][j]
    __shared__ __align__(16) float hcp[32 * HCP_STRIDE];  // padded h+cond
    __shared__ __align__(16) float actS[32 * 26];         // act / s
    __shared__ __align__(16) float skS[32 * 26];          // skip (written once)

    const int tid = threadIdx.x, chain = blockIdx.x;
    const int lane = tid & 31, warp = tid >> 5;
    const int j0 = warp * 6;          // A/conv/E/F tile
    const int d2 = tid >> 1;          // G rows d2, d2+64
    const int jg = (tid & 1) * 12;    // G j tile

    // load z_init -> xs
    {
        const float4* zp = (const float4*)(z_init + (size_t)chain * 3072);
#pragma unroll
        for (int q = 0; q < 6; q++) {
            float4 v = zp[tid * 6 + q];
            int j = q * 4;
            xs[tid * 26 + j] = v.x; xs[tid * 26 + j + 1] = v.y;
            xs[tid * 26 + j + 2] = v.z; xs[tid * 26 + j + 3] = v.w;
        }
    }
    for (int i = tid; i < 32 * HCP_STRIDE; i += 128) hcp[i] = 0.f;
    __syncthreads();

    const float bin_l = b_in[lane];
    const float bo1_l = b_o1[lane];
    const float bo2_a = b_o2[d2], bo2_b = b_o2[d2 + 64];
    const u64 HALF2 = pack2(0.70710678118654752f, 0.70710678118654752f);

    u64 h[3], skp[3];

    for (int t = NSTEPS - 1; t >= 0; t--) {
        const float s1m = g_coef[t * 5 + 0], isab = g_coef[t * 5 + 1];
        const float c0 = g_coef[t * 5 + 2], cxt = g_coef[t * 5 + 3], sg = g_coef[t * 5 + 4];

        // ---- A: h = relu(W_in @ x + b); write hcp for layer 0 ----
        {
            u64 acc0 = pack2(bin_l, bin_l), acc1 = acc0, acc2 = acc0;
#pragma unroll 4
            for (int d = 0; d < 128; d++) {
                u64 w = *(const u64*)(w_inT2 + d * 32 + lane);
                const float* xp = &xs[d * 26 + j0];
                acc0 = fma2(w, *(const u64*)(xp), acc0);
                acc1 = fma2(w, *(const u64*)(xp + 2), acc1);
                acc2 = fma2(w, *(const u64*)(xp + 4), acc2);
            }
            float cnd = g_cond[t * 32 + lane];  // l = 0
            u64 cnd2 = pack2(cnd, cnd);
            u64 acc[3] = {acc0, acc1, acc2};
#pragma unroll
            for (int p = 0; p < 3; p++) {
                float2 v = unpk(acc[p]);
                h[p] = pack2(fmaxf(v.x, 0.f), fmaxf(v.y, 0.f));
                *(u64*)&hcp[lane * HCP_STRIDE + 32 + j0 + 2 * p] = add2(h[p], cnd2);
                skp[p] = 0ULL;
            }
        }
        __syncthreads();

        // ---- residual layers ----
        for (int l = 0; l < 6; l++) {
            // conv + gating fused
            {
                float bg = bdil[l * 64 + lane], bf = bdil[l * 64 + 32 + lane];
                u64 ag[3] = {pack2(bg, bg), pack2(bg, bg), pack2(bg, bg)};
                u64 af[3] = {pack2(bf, bf), pack2(bf, bf), pack2(bf, bf)};
                const float2* wbase = wdilT2 + l * (32 * 3 * 64) + lane;
                switch (l) {
                    case 0: conv_pair<1>(wbase, hcp, j0, ag, af); break;
                    case 1: conv_pair<2>(wbase, hcp, j0, ag, af); break;
                    case 2: conv_pair<4>(wbase, hcp, j0, ag, af); break;
                    case 3: conv_pair<8>(wbase, hcp, j0, ag, af); break;
                    case 4: conv_pair<16>(wbase, hcp, j0, ag, af); break;
                    default: conv_pair<32>(wbase, hcp, j0, ag, af); break;
                }
#pragma unroll
                for (int p = 0; p < 3; p++) {
                    float2 g = unpk(ag[p]), f = unpk(af[p]);
                    *(u64*)&actS[lane * 26 + j0 + 2 * p] =
                        pack2(tanh_f(f.x) * sigm_f(g.x), tanh_f(f.y) * sigm_f(g.y));
                }
            }
            __syncthreads();

            // E: res/skip GEMM + h, skip register updates, write next hcp
            {
                float br = bout[l * 64 + lane], bs = bout[l * 64 + 32 + lane];
                u64 ar[3] = {pack2(br, br), pack2(br, br), pack2(br, br)};
                u64 as_[3] = {pack2(bs, bs), pack2(bs, bs), pack2(bs, bs)};
                const float2* wo = woutT2 + l * (32 * 64) + lane;
#pragma unroll 8
                for (int c = 0; c < 32; c++) {
                    u64 wr = *(const u64*)(wo + c * 64);
                    u64 ws = *(const u64*)(wo + c * 64 + 32);
                    const float* ap = &actS[c * 26 + j0];
#pragma unroll
                    for (int p = 0; p < 3; p++) {
                        u64 a = *(const u64*)(ap + 2 * p);
                        ar[p] = fma2(wr, a, ar[p]);
                        as_[p] = fma2(ws, a, as_[p]);
                    }
                }
                if (l < 5) {
                    float cn = g_cond[((l + 1) * NSTEPS + t) * 32 + lane];
                    u64 cn2 = pack2(cn, cn);
#pragma unroll
                    for (int p = 0; p < 3; p++) {
                        h[p] = mul2(add2(h[p], ar[p]), HALF2);
                        skp[p] = add2(skp[p], as_[p]);
                        *(u64*)&hcp[lane * HCP_STRIDE + 32 + j0 + 2 * p] = add2(h[p], cn2);
                    }
                } else {
#pragma unroll
                    for (int p = 0; p < 3; p++) {
                        skp[p] = add2(skp[p], as_[p]);
                        *(u64*)&skS[lane * 26 + j0 + 2 * p] = skp[p];
                    }
                }
            }
            __syncthreads();
        }

        // ---- F: s = relu(W_o1 @ skip/sqrt6 + b) -> actS ----
        {
            u64 sa[3] = {pack2(bo1_l, bo1_l), pack2(bo1_l, bo1_l), pack2(bo1_l, bo1_l)};
#pragma unroll 8
            for (int c = 0; c < 32; c++) {
                u64 w = *(const u64*)(w_o1T2 + c * 32 + lane);
                const float* sp = &skS[c * 26 + j0];
                sa[0] = fma2(w, *(const u64*)(sp), sa[0]);
                sa[1] = fma2(w, *(const u64*)(sp + 2), sa[1]);
                sa[2] = fma2(w, *(const u64*)(sp + 4), sa[2]);
            }
#pragma unroll
            for (int p = 0; p < 3; p++) {
                float2 v = unpk(sa[p]);
                *(u64*)&actS[lane * 26 + j0 + 2 * p] = pack2(fmaxf(v.x, 0.f), fmaxf(v.y, 0.f));
            }
        }
        __syncthreads();

        // ---- G: eps = W_o2 @ s + b for rows d2, d2+64; DDPM update ----
        {
            u64 ea[6], eb[6];
            u64 ba2 = pack2(bo2_a, bo2_a), bb2 = pack2(bo2_b, bo2_b);
#pragma unroll
            for (int p = 0; p < 6; p++) { ea[p] = ba2; eb[p] = bb2; }
#pragma unroll 8
            for (int c = 0; c < 32; c++) {
                u64 wA = *(const u64*)(w_o2T2 + c * 128 + d2);
                u64 wB = *(const u64*)(w_o2T2 + c * 128 + d2 + 64);
                const float* sp = &actS[c * 26 + jg];
#pragma unroll
                for (int p = 0; p < 6; p++) {
                    u64 s = *(const u64*)(sp + 2 * p);
                    ea[p] = fma2(wA, s, ea[p]);
                    eb[p] = fma2(wB, s, eb[p]);
                }
            }
            const float* nzb = noise + ((size_t)(NSTEPS - 1 - t) * 512 + chain) * 3072;
#pragma unroll
            for (int r = 0; r < 2; r++) {
                int d = d2 + r * 64;
                const u64* acc = r ? eb : ea;
                const float4* np = (const float4*)(nzb + d * 24 + jg);
                float4 n0 = np[0], n1 = np[1], n2 = np[2];
                float nz[12] = {n0.x, n0.y, n0.z, n0.w, n1.x, n1.y, n1.z, n1.w,
                                n2.x, n2.y, n2.z, n2.w};
                float* xp = &xs[d * 26 + jg];
#pragma unroll
                for (int p = 0; p < 6; p++) {
                    float2 e = unpk(acc[p]);
                    float xa = xp[2 * p], xb2 = xp[2 * p + 1];
                    float x0a = (xa - s1m * e.x) * isab;
                    float x0b = (xb2 - s1m * e.y) * isab;
                    x0a = fminf(fmaxf(x0a, -1.f), 1.f);
                    x0b = fminf(fmaxf(x0b, -1.f), 1.f);
                    xp[2 * p]     = fmaf(c0, x0a, fmaf(cxt, xa, sg * nz[2 * p]));
                    xp[2 * p + 1] = fmaf(c0, x0b, fmaf(cxt, xb2, sg * nz[2 * p + 1]));
                }
            }
        }
        __syncthreads();
    }

    // ---- final: Gaussian -> Student-t4 marginal transform ----
    {
        int b = chain & 31;
        float lc = g_loc[b * 128 + tid];
        float scl = g_scale[b * 128 + tid];
        for (int hh = 0; hh < 24; hh++) {
            double z = (double)xs[tid * 26 + hh];
            double u = 0.5 * erfc(-z * 0.70710678118654752440);
            u = fmin(fmax(u, 1e-6), 1.0 - 1e-6);
            double a = 4.0 * u * (1.0 - u);
            a = fmin(fmax(a, 1e-12), 1.0);
            double r = sqrt(a);
            double q = 2.0 * sqrt(fmax(cos(acos(r) / 3.0) / r - 1.0, 0.0));
            double sgn = (u >= 0.5) ? 1.0 : -1.0;
            out[((size_t)chain * 24 + hh) * 128 + tid] = (float)((double)lc + (double)scl * sgn * q);
        }
    }
}

extern "C" void kernel_launch(void* const* d_in, const int* in_sizes, int n_in,
                              void* d_out, int out_size) {
    const float* x_hist = (const float*)d_in[0];
    const float* z_init = (const float*)d_in[1];
    const float* noise = (const float*)d_in[2];
    const float* w_in = (const float*)d_in[3];
    const float* b_in = (const float*)d_in[4];
    const float* tw1 = (const float*)d_in[5];
    const float* tb1 = (const float*)d_in[6];
    const float* tw2 = (const float*)d_in[7];
    const float* tb2 = (const float*)d_in[8];
    const float* lwt = (const float*)d_in[9];
    const float* lbt = (const float*)d_in[10];
    const float* lwd = (const float*)d_in[11];
    const float* lbd = (const float*)d_in[12];
    const float* lwo = (const float*)d_in[13];
    const float* lbo = (const float*)d_in[14];
    const float* w_o1 = (const float*)d_in[15];
    const float* b_o1 = (const float*)d_in[16];
    const float* w_o2 = (const float*)d_in[17];
    const float* b_o2 = (const float*)d_in[18];
    float* out = (float*)d_out;

    k_prep<<<64, 256>>>(w_in, lwd, lwo, w_o1, w_o2);
    k_stats<<<32, 128>>>(x_hist);
    k_temb<<<50, 512>>>(tw1, tb1, tw2, tb2, lwt, lbt);
    k_main<<<512, 128>>>(z_init, noise, b_in, lbd, lbo, b_o1, b_o2, out);
}

// round 5
// speedup vs baseline: 1.1337x; 1.1337x over previous
#include <cuda_runtime.h>
#include <cuda_bf16.h>
#include <math.h>

// ---------------------------------------------------------------------------
// 512 independent diffusion chains; one persistent CTA (128 thr) per chain.
// L1-wavefront-optimized: non-dup scalar weights (re-dup in regs), shared
// conv windows, aligned float4 shared traffic.
// ---------------------------------------------------------------------------

#define NSTEPS 50
#define HCP_STRIDE 90
#define ACT_STRIDE 28
#define XS_STRIDE  28
typedef unsigned long long u64;

// ---- device-global scratch (no allocations allowed) ----
__device__ float g_loc[32 * 128];
__device__ float g_scale[32 * 128];
__device__ float g_cond[6 * NSTEPS * 32];   // [l][t][c]
__device__ float g_coef[NSTEPS * 5];        // s1m, 1/sab, c0, cxt, sig
__device__ float w_inT[128 * 32];           // [d][c]
__device__ float wdilT[6 * 32 * 3 * 64];    // [l][c][k][o]
__device__ float woutT[6 * 32 * 64];        // [l][c][o]
__device__ float w_o1T[32 * 32];            // [c][o], pre-scaled 1/sqrt(6)
__device__ float w_o2T[32 * 128];           // [c][d]

// ---- packed f32x2 helpers ----
__device__ __forceinline__ u64 fma2(u64 a, u64 b, u64 c) {
    u64 d; asm("fma.rn.f32x2 %0, %1, %2, %3;" : "=l"(d) : "l"(a), "l"(b), "l"(c)); return d;
}
__device__ __forceinline__ u64 add2(u64 a, u64 b) {
    u64 d; asm("add.rn.f32x2 %0, %1, %2;" : "=l"(d) : "l"(a), "l"(b)); return d;
}
__device__ __forceinline__ u64 mul2(u64 a, u64 b) {
    u64 d; asm("mul.rn.f32x2 %0, %1, %2;" : "=l"(d) : "l"(a), "l"(b)); return d;
}
__device__ __forceinline__ u64 pack2(float lo, float hi) {
    u64 r; asm("mov.b64 %0, {%1, %2};" : "=l"(r) : "f"(lo), "f"(hi)); return r;
}
__device__ __forceinline__ u64 dup2(float w) { return pack2(w, w); }
__device__ __forceinline__ float2 unpk(u64 a) {
    float2 v; asm("mov.b64 {%0, %1}, %2;" : "=f"(v.x), "=f"(v.y) : "l"(a)); return v;
}
__device__ __forceinline__ float sigm_f(float x) { return 1.0f / (1.0f + __expf(-x)); }
__device__ __forceinline__ float tanh_f(float x) { return 1.0f - 2.0f / (__expf(2.0f * x) + 1.0f); }

// ---------------------------------------------------------------------------
// Setup: weight transposes (non-dup float) + DDPM schedule (double)
// ---------------------------------------------------------------------------
__global__ void k_prep(const float* __restrict__ w_in, const float* __restrict__ lwd,
                       const float* __restrict__ lwo, const float* __restrict__ w_o1,
                       const float* __restrict__ w_o2) {
    int i = blockIdx.x * blockDim.x + threadIdx.x;
    int nt = gridDim.x * blockDim.x;
    for (int idx = i; idx < 4096; idx += nt) {
        int d = idx >> 5, c = idx & 31;
        w_inT[idx] = w_in[c * 128 + d];
    }
    for (int idx = i; idx < 6 * 32 * 3 * 64; idx += nt) {
        int o = idx & 63, r = idx >> 6;
        int k = r % 3, r2 = r / 3;
        int c = r2 & 31, l = r2 >> 5;
        wdilT[idx] = lwd[((l * 64 + o) * 32 + c) * 3 + k];
    }
    for (int idx = i; idx < 6 * 32 * 64; idx += nt) {
        int o = idx & 63, r = idx >> 6;
        int c = r & 31, l = r >> 5;
        woutT[idx] = lwo[(l * 64 + o) * 32 + c];
    }
    for (int idx = i; idx < 1024; idx += nt) {
        int o = idx & 31, c = idx >> 5;
        w_o1T[idx] = w_o1[o * 32 + c] * 0.40824829046386302f;  // 1/sqrt(6)
    }
    for (int idx = i; idx < 4096; idx += nt) {
        int d = idx & 127, c = idx >> 7;
        w_o2T[idx] = w_o2[d * 32 + c];
    }
    if (i == 0) {
        double abar = 1.0;
        for (int t = 0; t < NSTEPS; t++) {
            double beta = 1e-4 + (double)t * (0.1 - 1e-4) / 49.0;
            double alpha = 1.0 - beta;
            double abar_prev = abar;
            abar *= alpha;
            double om = 1.0 - abar;
            g_coef[t * 5 + 0] = (float)sqrt(om);
            g_coef[t * 5 + 1] = (float)(1.0 / sqrt(abar));
            g_coef[t * 5 + 2] = (float)(beta * sqrt(abar_prev) / om);
            g_coef[t * 5 + 3] = (float)((1.0 - abar_prev) * sqrt(alpha) / om);
            double pv = beta * (1.0 - abar_prev) / om;
            g_coef[t * 5 + 4] = (t > 0) ? (float)sqrt(pv) : 0.0f;
        }
    }
}

// ---------------------------------------------------------------------------
// Setup: EWMA Student-t marginal fit. grid 32 (b) x 128 (d)
// ---------------------------------------------------------------------------
__global__ void k_stats(const float* __restrict__ x_hist) {
    int b = blockIdx.x, d = threadIdx.x;
    const float* xb = x_hist + (size_t)b * 192 * 128 + d;
    double s = 0.0;
    for (int t = 0; t < 192; t++) s += (double)xb[t * 128];
    float mean = (float)(s / 192.0);
    float c = xb[0] - mean;
    float v = c * c;
    for (int t = 1; t < 192; t++) {
        float cc = xb[t * 128] - mean;
        v = 0.94f * v + 0.06f * (cc * cc);
    }
    g_loc[b * 128 + d] = mean;
    g_scale[b * 128 + d] = fmaxf(sqrtf(v * 0.5f), 1e-5f);
}

// ---------------------------------------------------------------------------
// Setup: step embedding + per-layer cond. grid 50 (t) x 512 threads.
// ---------------------------------------------------------------------------
__global__ void k_temb(const float* __restrict__ w1, const float* __restrict__ b1,
                       const float* __restrict__ w2, const float* __restrict__ b2,
                       const float* __restrict__ wt, const float* __restrict__ bt) {
    __shared__ float pe[128], te1[512], te2[512];
    int t = blockIdx.x, tid = threadIdx.x;
    if (tid < 64) {
        float y = ((float)tid * 4.0f) / 63.0f;
        float p = (float)pow(10.0, (double)y);
        float e = (float)t * p;
        pe[tid] = (float)sin((double)e);
        pe[tid + 64] = (float)cos((double)e);
    }
    __syncthreads();
    {
        double a = (double)b1[tid];
        for (int j = 0; j < 128; j++) a += (double)pe[j] * (double)w1[j * 512 + tid];
        te1[tid] = (float)(a / (1.0 + exp(-a)));
    }
    __syncthreads();
    {
        double a = (double)b2[tid];
        for (int k = 0; k < 512; k++) a += (double)te1[k] * (double)w2[k * 512 + tid];
        te2[tid] = (float)(a / (1.0 + exp(-a)));
    }
    __syncthreads();
    if (tid < 192) {
        int l = tid >> 5, c = tid & 31;
        double a = (double)bt[l * 32 + c];
        for (int k = 0; k < 512; k++) a += (double)te2[k] * (double)wt[(l * 512 + k) * 32 + c];
        g_cond[(l * NSTEPS + t) * 32 + c] = (float)a;
    }
}

// ---------------------------------------------------------------------------
// Dilated conv, gate+filt per thread (o = lane, j0 = warp*6).
// Window loads shared across taps for small dilations.
// ---------------------------------------------------------------------------
template <int DIL>
__device__ __forceinline__ void conv_pair(const float* __restrict__ wbase,
                                          const float* hcpS, int j0,
                                          u64 ag[3], u64 af[3]) {
#pragma unroll 4
    for (int c = 0; c < 32; c++) {
        const float* wr = wbase + c * 192;   // [k][o], o folded into wbase
        u64 wg0 = dup2(wr[0]),   wf0 = dup2(wr[32]);
        u64 wg1 = dup2(wr[64]),  wf1 = dup2(wr[96]);
        u64 wg2 = dup2(wr[128]), wf2 = dup2(wr[160]);
        const float* hp = hcpS + c * HCP_STRIDE + 32 + j0;
        u64 m0 = *(const u64*)(hp), m1 = *(const u64*)(hp + 2), m2 = *(const u64*)(hp + 4);
        u64 lv0, lv1, lv2, rv0, rv1, rv2;
        if (DIL == 1) {
            float xm1 = hp[-1], x6 = hp[6];
            float2 f0 = unpk(m0), f1 = unpk(m1), f2 = unpk(m2);
            lv0 = pack2(xm1, f0.x); lv1 = pack2(f0.y, f1.x); lv2 = pack2(f1.y, f2.x);
            rv0 = lv1; rv1 = lv2; rv2 = pack2(f2.y, x6);
        } else if (DIL == 2) {
            lv0 = *(const u64*)(hp - 2); lv1 = m0; lv2 = m1;
            rv0 = m1; rv1 = m2; rv2 = *(const u64*)(hp + 6);
        } else if (DIL == 4) {
            lv0 = *(const u64*)(hp - 4); lv1 = *(const u64*)(hp - 2); lv2 = m0;
            rv0 = m2; rv1 = *(const u64*)(hp + 6); rv2 = *(const u64*)(hp + 8);
        } else {
            lv0 = *(const u64*)(hp - DIL); lv1 = *(const u64*)(hp - DIL + 2);
            lv2 = *(const u64*)(hp - DIL + 4);
            rv0 = *(const u64*)(hp + DIL); rv1 = *(const u64*)(hp + DIL + 2);
            rv2 = *(const u64*)(hp + DIL + 4);
        }
        ag[0] = fma2(wg0, lv0, ag[0]); ag[1] = fma2(wg0, lv1, ag[1]); ag[2] = fma2(wg0, lv2, ag[2]);
        ag[0] = fma2(wg1, m0,  ag[0]); ag[1] = fma2(wg1, m1,  ag[1]); ag[2] = fma2(wg1, m2,  ag[2]);
        ag[0] = fma2(wg2, rv0, ag[0]); ag[1] = fma2(wg2, rv1, ag[1]); ag[2] = fma2(wg2, rv2, ag[2]);
        af[0] = fma2(wf0, lv0, af[0]); af[1] = fma2(wf0, lv1, af[1]); af[2] = fma2(wf0, lv2, af[2]);
        af[0] = fma2(wf1, m0,  af[0]); af[1] = fma2(wf1, m1,  af[1]); af[2] = fma2(wf1, m2,  af[2]);
        af[0] = fma2(wf2, rv0, af[0]); af[1] = fma2(wf2, rv1, af[1]); af[2] = fma2(wf2, rv2, af[2]);
    }
}

// ---------------------------------------------------------------------------
// Main persistent kernel: grid 512 (chain) x 128 threads.
// ---------------------------------------------------------------------------
__global__ __launch_bounds__(128, 4) void k_main(
    const float* __restrict__ z_init, const float* __restrict__ noise,
    const float* __restrict__ b_in, const float* __restrict__ bdil,
    const float* __restrict__ bout, const float* __restrict__ b_o1,
    const float* __restrict__ b_o2, float* __restrict__ out) {
    __shared__ __align__(16) float xs[128 * XS_STRIDE];    // x state [d][j]
    __shared__ __align__(16) float hcp[32 * HCP_STRIDE];   // padded h+cond
    __shared__ __align__(16) float actS[32 * ACT_STRIDE];  // act / s
    __shared__ __align__(16) float skS[32 * 26];           // skip (written once)

    const int tid = threadIdx.x, chain = blockIdx.x;
    const int lane = tid & 31, warp = tid >> 5;
    const int j0 = warp * 6;          // A/conv/E/F tile

    // load z_init -> xs (stride 28, 16B-aligned rows)
    {
        const float4* zp = (const float4*)(z_init + (size_t)chain * 3072);
#pragma unroll
        for (int q = 0; q < 6; q++) {
            float4 v = zp[tid * 6 + q];
            *(float4*)&xs[tid * XS_STRIDE + 4 * q] = v;
        }
    }
    for (int i = tid; i < 32 * HCP_STRIDE; i += 128) hcp[i] = 0.f;
    __syncthreads();

    const float bin_l = b_in[lane];
    const float bo1_l = b_o1[lane];
    const float bo2_d = b_o2[tid];
    const u64 HALF2 = pack2(0.70710678118654752f, 0.70710678118654752f);

    u64 h[3], skp[3];

    for (int t = NSTEPS - 1; t >= 0; t--) {
        const float s1m = g_coef[t * 5 + 0], isab = g_coef[t * 5 + 1];
        const float c0 = g_coef[t * 5 + 2], cxt = g_coef[t * 5 + 3], sg = g_coef[t * 5 + 4];

        // ---- A: h = relu(W_in @ x + b); write hcp for layer 0 ----
        {
            u64 acc0 = dup2(bin_l), acc1 = acc0, acc2 = acc0;
#pragma unroll 4
            for (int d = 0; d < 128; d++) {
                u64 w = dup2(w_inT[d * 32 + lane]);
                const float* xp = &xs[d * XS_STRIDE + j0];
                acc0 = fma2(w, *(const u64*)(xp), acc0);
                acc1 = fma2(w, *(const u64*)(xp + 2), acc1);
                acc2 = fma2(w, *(const u64*)(xp + 4), acc2);
            }
            float cnd = g_cond[t * 32 + lane];  // l = 0
            u64 cnd2 = dup2(cnd);
            u64 acc[3] = {acc0, acc1, acc2};
#pragma unroll
            for (int p = 0; p < 3; p++) {
                float2 v = unpk(acc[p]);
                h[p] = pack2(fmaxf(v.x, 0.f), fmaxf(v.y, 0.f));
                *(u64*)&hcp[lane * HCP_STRIDE + 32 + j0 + 2 * p] = add2(h[p], cnd2);
                skp[p] = 0ULL;
            }
        }
        __syncthreads();

        // ---- residual layers ----
        for (int l = 0; l < 6; l++) {
            // conv + gating fused
            {
                float bg = bdil[l * 64 + lane], bf = bdil[l * 64 + 32 + lane];
                u64 ag[3] = {dup2(bg), dup2(bg), dup2(bg)};
                u64 af[3] = {dup2(bf), dup2(bf), dup2(bf)};
                const float* wbase = wdilT + l * (32 * 3 * 64) + lane;
                switch (l) {
                    case 0: conv_pair<1>(wbase, hcp, j0, ag, af); break;
                    case 1: conv_pair<2>(wbase, hcp, j0, ag, af); break;
                    case 2: conv_pair<4>(wbase, hcp, j0, ag, af); break;
                    case 3: conv_pair<8>(wbase, hcp, j0, ag, af); break;
                    case 4: conv_pair<16>(wbase, hcp, j0, ag, af); break;
                    default: conv_pair<32>(wbase, hcp, j0, ag, af); break;
                }
#pragma unroll
                for (int p = 0; p < 3; p++) {
                    float2 g = unpk(ag[p]), f = unpk(af[p]);
                    *(u64*)&actS[lane * ACT_STRIDE + j0 + 2 * p] =
                        pack2(tanh_f(f.x) * sigm_f(g.x), tanh_f(f.y) * sigm_f(g.y));
                }
            }
            __syncthreads();

            // E: res/skip GEMM + h, skip register updates, write next hcp
            {
                float br = bout[l * 64 + lane], bs = bout[l * 64 + 32 + lane];
                u64 ar[3] = {dup2(br), dup2(br), dup2(br)};
                u64 as_[3] = {dup2(bs), dup2(bs), dup2(bs)};
                const float* wo = woutT + l * (32 * 64) + lane;
#pragma unroll 8
                for (int c = 0; c < 32; c++) {
                    u64 wr = dup2(wo[c * 64]);
                    u64 ws = dup2(wo[c * 64 + 32]);
                    const float* ap = &actS[c * ACT_STRIDE + j0];
#pragma unroll
                    for (int p = 0; p < 3; p++) {
                        u64 a = *(const u64*)(ap + 2 * p);
                        ar[p] = fma2(wr, a, ar[p]);
                        as_[p] = fma2(ws, a, as_[p]);
                    }
                }
                if (l < 5) {
                    float cn = g_cond[((l + 1) * NSTEPS + t) * 32 + lane];
                    u64 cn2 = dup2(cn);
#pragma unroll
                    for (int p = 0; p < 3; p++) {
                        h[p] = mul2(add2(h[p], ar[p]), HALF2);
                        skp[p] = add2(skp[p], as_[p]);
                        *(u64*)&hcp[lane * HCP_STRIDE + 32 + j0 + 2 * p] = add2(h[p], cn2);
                    }
                } else {
#pragma unroll
                    for (int p = 0; p < 3; p++) {
                        skp[p] = add2(skp[p], as_[p]);
                        *(u64*)&skS[lane * 26 + j0 + 2 * p] = skp[p];
                    }
                }
            }
            __syncthreads();
        }

        // ---- F: s = relu(W_o1 @ skip/sqrt6 + b) -> actS ----
        {
            u64 sa[3] = {dup2(bo1_l), dup2(bo1_l), dup2(bo1_l)};
#pragma unroll 8
            for (int c = 0; c < 32; c++) {
                u64 w = dup2(w_o1T[c * 32 + lane]);
                const float* sp = &skS[c * 26 + j0];
                sa[0] = fma2(w, *(const u64*)(sp), sa[0]);
                sa[1] = fma2(w, *(const u64*)(sp + 2), sa[1]);
                sa[2] = fma2(w, *(const u64*)(sp + 4), sa[2]);
            }
#pragma unroll
            for (int p = 0; p < 3; p++) {
                float2 v = unpk(sa[p]);
                *(u64*)&actS[lane * ACT_STRIDE + j0 + 2 * p] = pack2(fmaxf(v.x, 0.f), fmaxf(v.y, 0.f));
            }
        }
        __syncthreads();

        // ---- G: eps row d = tid, all 24 j; DDPM update of xs ----
        {
            u64 acc[12];
            u64 b2 = dup2(bo2_d);
#pragma unroll
            for (int p = 0; p < 12; p++) acc[p] = b2;
#pragma unroll 4
            for (int c = 0; c < 32; c++) {
                u64 w2 = dup2(w_o2T[c * 128 + tid]);
                const float4* sp = (const float4*)&actS[c * ACT_STRIDE];
#pragma unroll
                for (int q = 0; q < 6; q++) {
                    float4 v = sp[q];
                    acc[2 * q]     = fma2(w2, pack2(v.x, v.y), acc[2 * q]);
                    acc[2 * q + 1] = fma2(w2, pack2(v.z, v.w), acc[2 * q + 1]);
                }
            }
            const float4* np = (const float4*)(noise +
                ((size_t)(NSTEPS - 1 - t) * 512 + chain) * 3072 + (size_t)tid * 24);
            float* xp = &xs[tid * XS_STRIDE];
#pragma unroll
            for (int q = 0; q < 6; q++) {
                float4 nv = np[q];
                float4 xv = *(const float4*)&xp[4 * q];
                float2 e0 = unpk(acc[2 * q]);
                float2 e1 = unpk(acc[2 * q + 1]);
                float4 r;
                {
                    float x0 = (xv.x - s1m * e0.x) * isab;
                    x0 = fminf(fmaxf(x0, -1.f), 1.f);
                    r.x = fmaf(c0, x0, fmaf(cxt, xv.x, sg * nv.x));
                }
                {
                    float x0 = (xv.y - s1m * e0.y) * isab;
                    x0 = fminf(fmaxf(x0, -1.f), 1.f);
                    r.y = fmaf(c0, x0, fmaf(cxt, xv.y, sg * nv.y));
                }
                {
                    float x0 = (xv.z - s1m * e1.x) * isab;
                    x0 = fminf(fmaxf(x0, -1.f), 1.f);
                    r.z = fmaf(c0, x0, fmaf(cxt, xv.z, sg * nv.z));
                }
                {
                    float x0 = (xv.w - s1m * e1.y) * isab;
                    x0 = fminf(fmaxf(x0, -1.f), 1.f);
                    r.w = fmaf(c0, x0, fmaf(cxt, xv.w, sg * nv.w));
                }
                *(float4*)&xp[4 * q] = r;
            }
        }
        __syncthreads();
    }

    // ---- final: Gaussian -> Student-t4 marginal transform ----
    {
        int b = chain & 31;
        float lc = g_loc[b * 128 + tid];
        float scl = g_scale[b * 128 + tid];
        for (int hh = 0; hh < 24; hh++) {
            double z = (double)xs[tid * XS_STRIDE + hh];
            double u = 0.5 * erfc(-z * 0.70710678118654752440);
            u = fmin(fmax(u, 1e-6), 1.0 - 1e-6);
            double a = 4.0 * u * (1.0 - u);
            a = fmin(fmax(a, 1e-12), 1.0);
            double r = sqrt(a);
            double q = 2.0 * sqrt(fmax(cos(acos(r) / 3.0) / r - 1.0, 0.0));
            double sgn = (u >= 0.5) ? 1.0 : -1.0;
            out[((size_t)chain * 24 + hh) * 128 + tid] = (float)((double)lc + (double)scl * sgn * q);
        }
    }
}

extern "C" void kernel_launch(void* const* d_in, const int* in_sizes, int n_in,
                              void* d_out, int out_size) {
    const float* x_hist = (const float*)d_in[0];
    const float* z_init = (const float*)d_in[1];
    const float* noise = (const float*)d_in[2];
    const float* w_in = (const float*)d_in[3];
    const float* b_in = (const float*)d_in[4];
    const float* tw1 = (const float*)d_in[5];
    const float* tb1 = (const float*)d_in[6];
    const float* tw2 = (const float*)d_in[7];
    const float* tb2 = (const float*)d_in[8];
    const float* lwt = (const float*)d_in[9];
    const float* lbt = (const float*)d_in[10];
    const float* lwd = (const float*)d_in[11];
    const float* lbd = (const float*)d_in[12];
    const float* lwo = (const float*)d_in[13];
    const float* lbo = (const float*)d_in[14];
    const float* w_o1 = (const float*)d_in[15];
    const float* b_o1 = (const float*)d_in[16];
    const float* w_o2 = (const float*)d_in[17];
    const float* b_o2 = (const float*)d_in[18];
    float* out = (float*)d_out;

    k_prep<<<64, 256>>>(w_in, lwd, lwo, w_o1, w_o2);
    k_stats<<<32, 128>>>(x_hist);
    k_temb<<<50, 512>>>(tw1, tb1, tw2, tb2, lwt, lbt);
    k_main<<<512, 128>>>(z_init, noise, b_in, lbd, lbo, b_o1, b_o2, out);
}

// round 6
// speedup vs baseline: 1.2038x; 1.0618x over previous
#include <cuda_runtime.h>
#include <cuda_bf16.h>
#include <math.h>

// ---------------------------------------------------------------------------
// 512 independent diffusion chains; one persistent CTA (128 thr) per chain.
// Pair-packed weights (1 LDG.64 -> 2 fma2 streams), cp.async noise prefetch.
// ---------------------------------------------------------------------------

#define NSTEPS 50
#define HCP_STRIDE 90
#define ACT_STRIDE 28
#define XS_STRIDE  28
#define NZ_STRIDE  28
typedef unsigned long long u64;

// ---- device-global scratch (no allocations allowed) ----
__device__ float  g_loc[32 * 128];
__device__ float  g_scale[32 * 128];
__device__ float  g_cond[6 * NSTEPS * 32];   // [l][t][c]
__device__ float  g_coef[NSTEPS * 5];        // s1m, 1/sab, c0, cxt, sig
__device__ float2 w_inP[64 * 32];            // [d/2][c] -> (w[d], w[d+1])
__device__ float2 wdilP[6 * 32 * 3 * 32];    // [l][c][k][o] -> (gate, filt)
__device__ float2 woutP[6 * 32 * 32];        // [l][c][o] -> (res, skip)
__device__ float2 w_o1P[16 * 32];            // [c/2][o] -> (w[c], w[c+1]) /sqrt6
__device__ float2 w_o2P[16 * 128];           // [c/2][d] -> (w[c], w[c+1])

// ---- packed f32x2 helpers ----
__device__ __forceinline__ u64 fma2(u64 a, u64 b, u64 c) {
    u64 d; asm("fma.rn.f32x2 %0, %1, %2, %3;" : "=l"(d) : "l"(a), "l"(b), "l"(c)); return d;
}
__device__ __forceinline__ u64 add2(u64 a, u64 b) {
    u64 d; asm("add.rn.f32x2 %0, %1, %2;" : "=l"(d) : "l"(a), "l"(b)); return d;
}
__device__ __forceinline__ u64 mul2(u64 a, u64 b) {
    u64 d; asm("mul.rn.f32x2 %0, %1, %2;" : "=l"(d) : "l"(a), "l"(b)); return d;
}
__device__ __forceinline__ u64 pack2(float lo, float hi) {
    u64 r; asm("mov.b64 %0, {%1, %2};" : "=l"(r) : "f"(lo), "f"(hi)); return r;
}
__device__ __forceinline__ u64 dup2(float w) { return pack2(w, w); }
__device__ __forceinline__ float2 unpk(u64 a) {
    float2 v; asm("mov.b64 {%0, %1}, %2;" : "=f"(v.x), "=f"(v.y) : "l"(a)); return v;
}
__device__ __forceinline__ float sigm_f(float x) { return 1.0f / (1.0f + __expf(-x)); }
__device__ __forceinline__ float tanh_f(float x) { return 1.0f - 2.0f / (__expf(2.0f * x) + 1.0f); }
__device__ __forceinline__ void cpasync16(unsigned dst, const void* src) {
    asm volatile("cp.async.ca.shared.global [%0], [%1], 16;" :: "r"(dst), "l"(src));
}

// ---------------------------------------------------------------------------
// Setup: pair-packed weight transposes + DDPM schedule (double)
// ---------------------------------------------------------------------------
__global__ void k_prep(const float* __restrict__ w_in, const float* __restrict__ lwd,
                       const float* __restrict__ lwo, const float* __restrict__ w_o1,
                       const float* __restrict__ w_o2) {
    int i = blockIdx.x * blockDim.x + threadIdx.x;
    int nt = gridDim.x * blockDim.x;
    for (int idx = i; idx < 64 * 32; idx += nt) {
        int d2 = idx >> 5, c = idx & 31;
        w_inP[idx] = make_float2(w_in[c * 128 + 2 * d2], w_in[c * 128 + 2 * d2 + 1]);
    }
    for (int idx = i; idx < 6 * 32 * 3 * 32; idx += nt) {
        int o = idx & 31, r = idx >> 5;
        int k = r % 3, r2 = r / 3;
        int c = r2 & 31, l = r2 >> 5;
        wdilP[idx] = make_float2(lwd[((l * 64 + o) * 32 + c) * 3 + k],
                                 lwd[((l * 64 + 32 + o) * 32 + c) * 3 + k]);
    }
    for (int idx = i; idx < 6 * 32 * 32; idx += nt) {
        int o = idx & 31, r = idx >> 5;
        int c = r & 31, l = r >> 5;
        woutP[idx] = make_float2(lwo[(l * 64 + o) * 32 + c],
                                 lwo[(l * 64 + 32 + o) * 32 + c]);
    }
    for (int idx = i; idx < 16 * 32; idx += nt) {
        int o = idx & 31, c2 = idx >> 5;
        const float s = 0.40824829046386302f;  // 1/sqrt(6)
        w_o1P[idx] = make_float2(w_o1[o * 32 + 2 * c2] * s, w_o1[o * 32 + 2 * c2 + 1] * s);
    }
    for (int idx = i; idx < 16 * 128; idx += nt) {
        int d = idx & 127, c2 = idx >> 7;
        w_o2P[idx] = make_float2(w_o2[d * 32 + 2 * c2], w_o2[d * 32 + 2 * c2 + 1]);
    }
    if (i == 0) {
        double abar = 1.0;
        for (int t = 0; t < NSTEPS; t++) {
            double beta = 1e-4 + (double)t * (0.1 - 1e-4) / 49.0;
            double alpha = 1.0 - beta;
            double abar_prev = abar;
            abar *= alpha;
            double om = 1.0 - abar;
            g_coef[t * 5 + 0] = (float)sqrt(om);
            g_coef[t * 5 + 1] = (float)(1.0 / sqrt(abar));
            g_coef[t * 5 + 2] = (float)(beta * sqrt(abar_prev) / om);
            g_coef[t * 5 + 3] = (float)((1.0 - abar_prev) * sqrt(alpha) / om);
            double pv = beta * (1.0 - abar_prev) / om;
            g_coef[t * 5 + 4] = (t > 0) ? (float)sqrt(pv) : 0.0f;
        }
    }
}

// ---------------------------------------------------------------------------
// Setup: EWMA Student-t marginal fit. grid 32 (b) x 128 (d)
// ---------------------------------------------------------------------------
__global__ void k_stats(const float* __restrict__ x_hist) {
    int b = blockIdx.x, d = threadIdx.x;
    const float* xb = x_hist + (size_t)b * 192 * 128 + d;
    double s = 0.0;
    for (int t = 0; t < 192; t++) s += (double)xb[t * 128];
    float mean = (float)(s / 192.0);
    float c = xb[0] - mean;
    float v = c * c;
    for (int t = 1; t < 192; t++) {
        float cc = xb[t * 128] - mean;
        v = 0.94f * v + 0.06f * (cc * cc);
    }
    g_loc[b * 128 + d] = mean;
    g_scale[b * 128 + d] = fmaxf(sqrtf(v * 0.5f), 1e-5f);
}

// ---------------------------------------------------------------------------
// Setup: step embedding + per-layer cond. grid 50 (t) x 512 threads.
// ---------------------------------------------------------------------------
__global__ void k_temb(const float* __restrict__ w1, const float* __restrict__ b1,
                       const float* __restrict__ w2, const float* __restrict__ b2,
                       const float* __restrict__ wt, const float* __restrict__ bt) {
    __shared__ float pe[128], te1[512], te2[512];
    int t = blockIdx.x, tid = threadIdx.x;
    if (tid < 64) {
        float y = ((float)tid * 4.0f) / 63.0f;
        float p = (float)pow(10.0, (double)y);
        float e = (float)t * p;
        pe[tid] = (float)sin((double)e);
        pe[tid + 64] = (float)cos((double)e);
    }
    __syncthreads();
    {
        double a = (double)b1[tid];
        for (int j = 0; j < 128; j++) a += (double)pe[j] * (double)w1[j * 512 + tid];
        te1[tid] = (float)(a / (1.0 + exp(-a)));
    }
    __syncthreads();
    {
        double a = (double)b2[tid];
        for (int k = 0; k < 512; k++) a += (double)te1[k] * (double)w2[k * 512 + tid];
        te2[tid] = (float)(a / (1.0 + exp(-a)));
    }
    __syncthreads();
    if (tid < 192) {
        int l = tid >> 5, c = tid & 31;
        double a = (double)bt[l * 32 + c];
        for (int k = 0; k < 512; k++) a += (double)te2[k] * (double)wt[(l * 512 + k) * 32 + c];
        g_cond[(l * NSTEPS + t) * 32 + c] = (float)a;
    }
}

// ---------------------------------------------------------------------------
// Dilated conv, gate+filt per thread (o = lane, j0 = warp*6).
// Weights pair-packed: 3 LDG.64 per c-iter. Windows broadcast LDS.
// ---------------------------------------------------------------------------
template <int DIL>
__device__ __forceinline__ void conv_pair(const float2* __restrict__ wbase,
                                          const float* hcpS, int j0,
                                          u64 ag[3], u64 af[3]) {
#pragma unroll 4
    for (int c = 0; c < 32; c++) {
        const float2* wr = wbase + c * 96;
        float2 k0 = wr[0], k1 = wr[32], k2 = wr[64];
        u64 wg0 = dup2(k0.x), wf0 = dup2(k0.y);
        u64 wg1 = dup2(k1.x), wf1 = dup2(k1.y);
        u64 wg2 = dup2(k2.x), wf2 = dup2(k2.y);
        const float* hp = hcpS + c * HCP_STRIDE + 32 + j0;
        u64 m0 = *(const u64*)(hp), m1 = *(const u64*)(hp + 2), m2 = *(const u64*)(hp + 4);
        u64 lv0, lv1, lv2, rv0, rv1, rv2;
        if (DIL == 1) {
            float xm1 = hp[-1], x6 = hp[6];
            float2 f0 = unpk(m0), f1 = unpk(m1), f2 = unpk(m2);
            lv0 = pack2(xm1, f0.x); lv1 = pack2(f0.y, f1.x); lv2 = pack2(f1.y, f2.x);
            rv0 = lv1; rv1 = lv2; rv2 = pack2(f2.y, x6);
        } else if (DIL == 2) {
            lv0 = *(const u64*)(hp - 2); lv1 = m0; lv2 = m1;
            rv0 = m1; rv1 = m2; rv2 = *(const u64*)(hp + 6);
        } else if (DIL == 4) {
            lv0 = *(const u64*)(hp - 4); lv1 = *(const u64*)(hp - 2); lv2 = m0;
            rv0 = m2; rv1 = *(const u64*)(hp + 6); rv2 = *(const u64*)(hp + 8);
        } else {
            lv0 = *(const u64*)(hp - DIL); lv1 = *(const u64*)(hp - DIL + 2);
            lv2 = *(const u64*)(hp - DIL + 4);
            rv0 = *(const u64*)(hp + DIL); rv1 = *(const u64*)(hp + DIL + 2);
            rv2 = *(const u64*)(hp + DIL + 4);
        }
        ag[0] = fma2(wg0, lv0, ag[0]); ag[1] = fma2(wg0, lv1, ag[1]); ag[2] = fma2(wg0, lv2, ag[2]);
        ag[0] = fma2(wg1, m0,  ag[0]); ag[1] = fma2(wg1, m1,  ag[1]); ag[2] = fma2(wg1, m2,  ag[2]);
        ag[0] = fma2(wg2, rv0, ag[0]); ag[1] = fma2(wg2, rv1, ag[1]); ag[2] = fma2(wg2, rv2, ag[2]);
        af[0] = fma2(wf0, lv0, af[0]); af[1] = fma2(wf0, lv1, af[1]); af[2] = fma2(wf0, lv2, af[2]);
        af[0] = fma2(wf1, m0,  af[0]); af[1] = fma2(wf1, m1,  af[1]); af[2] = fma2(wf1, m2,  af[2]);
        af[0] = fma2(wf2, rv0, af[0]); af[1] = fma2(wf2, rv1, af[1]); af[2] = fma2(wf2, rv2, af[2]);
    }
}

// ---------------------------------------------------------------------------
// Main persistent kernel: grid 512 (chain) x 128 threads.
// ---------------------------------------------------------------------------
__global__ __launch_bounds__(128, 4) void k_main(
    const float* __restrict__ z_init, const float* __restrict__ noise,
    const float* __restrict__ b_in, const float* __restrict__ bdil,
    const float* __restrict__ bout, const float* __restrict__ b_o1,
    const float* __restrict__ b_o2, float* __restrict__ out) {
    __shared__ __align__(16) float xs[128 * XS_STRIDE];    // x state [d][j]
    __shared__ __align__(16) float hcp[32 * HCP_STRIDE];   // padded h+cond
    __shared__ __align__(16) float actS[32 * ACT_STRIDE];  // act / s
    __shared__ __align__(16) float skS[32 * 26];           // skip (written once)
    __shared__ __align__(16) float nzS[128 * NZ_STRIDE];   // prefetched noise

    const int tid = threadIdx.x, chain = blockIdx.x;
    const int lane = tid & 31, warp = tid >> 5;
    const int j0 = warp * 6;

    const unsigned nz_dst = (unsigned)__cvta_generic_to_shared(&nzS[tid * NZ_STRIDE]);

    // load z_init -> xs (stride 28, 16B-aligned rows)
    {
        const float4* zp = (const float4*)(z_init + (size_t)chain * 3072);
#pragma unroll
        for (int q = 0; q < 6; q++) {
            float4 v = zp[tid * 6 + q];
            *(float4*)&xs[tid * XS_STRIDE + 4 * q] = v;
        }
    }
    for (int i = tid; i < 32 * HCP_STRIDE; i += 128) hcp[i] = 0.f;
    __syncthreads();

    const float bin_l = b_in[lane];
    const float bo1_l = b_o1[lane];
    const float bo2_d = b_o2[tid];
    const u64 HALF2 = pack2(0.70710678118654752f, 0.70710678118654752f);

    u64 h[3], skp[3];

    for (int t = NSTEPS - 1; t >= 0; t--) {
        const float s1m = g_coef[t * 5 + 0], isab = g_coef[t * 5 + 1];
        const float c0 = g_coef[t * 5 + 2], cxt = g_coef[t * 5 + 3], sg = g_coef[t * 5 + 4];

        // ---- prefetch this step's noise into SMEM (used in phase G) ----
        {
            const float* nsrc = noise + ((size_t)(NSTEPS - 1 - t) * 512 + chain) * 3072 +
                                (size_t)tid * 24;
#pragma unroll
            for (int q = 0; q < 6; q++) cpasync16(nz_dst + 16 * q, nsrc + 4 * q);
            asm volatile("cp.async.commit_group;");
        }

        // ---- A: h = relu(W_in @ x + b); write hcp for layer 0 ----
        {
            u64 acc0 = dup2(bin_l), acc1 = acc0, acc2 = acc0;
#pragma unroll 4
            for (int d2 = 0; d2 < 64; d2++) {
                float2 w = w_inP[d2 * 32 + lane];
                u64 wx = dup2(w.x), wy = dup2(w.y);
                const float* xp = &xs[(2 * d2) * XS_STRIDE + j0];
                const float* xq = xp + XS_STRIDE;
                acc0 = fma2(wx, *(const u64*)(xp), acc0);
                acc1 = fma2(wx, *(const u64*)(xp + 2), acc1);
                acc2 = fma2(wx, *(const u64*)(xp + 4), acc2);
                acc0 = fma2(wy, *(const u64*)(xq), acc0);
                acc1 = fma2(wy, *(const u64*)(xq + 2), acc1);
                acc2 = fma2(wy, *(const u64*)(xq + 4), acc2);
            }
            float cnd = g_cond[t * 32 + lane];  // l = 0
            u64 cnd2 = dup2(cnd);
            u64 acc[3] = {acc0, acc1, acc2};
#pragma unroll
            for (int p = 0; p < 3; p++) {
                float2 v = unpk(acc[p]);
                h[p] = pack2(fmaxf(v.x, 0.f), fmaxf(v.y, 0.f));
                *(u64*)&hcp[lane * HCP_STRIDE + 32 + j0 + 2 * p] = add2(h[p], cnd2);
                skp[p] = 0ULL;
            }
        }
        __syncthreads();

        // ---- residual layers ----
        for (int l = 0; l < 6; l++) {
            // conv + gating fused
            {
                float bg = bdil[l * 64 + lane], bf = bdil[l * 64 + 32 + lane];
                u64 ag[3] = {dup2(bg), dup2(bg), dup2(bg)};
                u64 af[3] = {dup2(bf), dup2(bf), dup2(bf)};
                const float2* wbase = wdilP + l * (32 * 3 * 32) + lane;
                switch (l) {
                    case 0: conv_pair<1>(wbase, hcp, j0, ag, af); break;
                    case 1: conv_pair<2>(wbase, hcp, j0, ag, af); break;
                    case 2: conv_pair<4>(wbase, hcp, j0, ag, af); break;
                    case 3: conv_pair<8>(wbase, hcp, j0, ag, af); break;
                    case 4: conv_pair<16>(wbase, hcp, j0, ag, af); break;
                    default: conv_pair<32>(wbase, hcp, j0, ag, af); break;
                }
#pragma unroll
                for (int p = 0; p < 3; p++) {
                    float2 g = unpk(ag[p]), f = unpk(af[p]);
                    *(u64*)&actS[lane * ACT_STRIDE + j0 + 2 * p] =
                        pack2(tanh_f(f.x) * sigm_f(g.x), tanh_f(f.y) * sigm_f(g.y));
                }
            }
            __syncthreads();

            // E: res/skip GEMM + register h/skip updates, write next hcp
            {
                float br = bout[l * 64 + lane], bs = bout[l * 64 + 32 + lane];
                u64 ar[3] = {dup2(br), dup2(br), dup2(br)};
                u64 as_[3] = {dup2(bs), dup2(bs), dup2(bs)};
                const float2* wo = woutP + l * (32 * 32) + lane;
#pragma unroll 8
                for (int c = 0; c < 32; c++) {
                    float2 w = wo[c * 32];
                    u64 wr = dup2(w.x), ws = dup2(w.y);
                    const float* ap = &actS[c * ACT_STRIDE + j0];
#pragma unroll
                    for (int p = 0; p < 3; p++) {
                        u64 a = *(const u64*)(ap + 2 * p);
                        ar[p] = fma2(wr, a, ar[p]);
                        as_[p] = fma2(ws, a, as_[p]);
                    }
                }
                if (l < 5) {
                    float cn = g_cond[((l + 1) * NSTEPS + t) * 32 + lane];
                    u64 cn2 = dup2(cn);
#pragma unroll
                    for (int p = 0; p < 3; p++) {
                        h[p] = mul2(add2(h[p], ar[p]), HALF2);
                        skp[p] = add2(skp[p], as_[p]);
                        *(u64*)&hcp[lane * HCP_STRIDE + 32 + j0 + 2 * p] = add2(h[p], cn2);
                    }
                } else {
#pragma unroll
                    for (int p = 0; p < 3; p++) {
                        skp[p] = add2(skp[p], as_[p]);
                        *(u64*)&skS[lane * 26 + j0 + 2 * p] = skp[p];
                    }
                }
            }
            __syncthreads();
        }

        // ---- F: s = relu(W_o1 @ skip/sqrt6 + b) -> actS ----
        {
            u64 sa[3] = {dup2(bo1_l), dup2(bo1_l), dup2(bo1_l)};
#pragma unroll 8
            for (int c2 = 0; c2 < 16; c2++) {
                float2 w = w_o1P[c2 * 32 + lane];
                u64 wx = dup2(w.x), wy = dup2(w.y);
                const float* sp = &skS[(2 * c2) * 26 + j0];
                const float* sq = sp + 26;
                sa[0] = fma2(wx, *(const u64*)(sp), sa[0]);
                sa[1] = fma2(wx, *(const u64*)(sp + 2), sa[1]);
                sa[2] = fma2(wx, *(const u64*)(sp + 4), sa[2]);
                sa[0] = fma2(wy, *(const u64*)(sq), sa[0]);
                sa[1] = fma2(wy, *(const u64*)(sq + 2), sa[1]);
                sa[2] = fma2(wy, *(const u64*)(sq + 4), sa[2]);
            }
#pragma unroll
            for (int p = 0; p < 3; p++) {
                float2 v = unpk(sa[p]);
                *(u64*)&actS[lane * ACT_STRIDE + j0 + 2 * p] = pack2(fmaxf(v.x, 0.f), fmaxf(v.y, 0.f));
            }
        }
        __syncthreads();

        // ---- G: eps row d = tid, all 24 j; DDPM update of xs ----
        {
            u64 acc[12];
            u64 b2 = dup2(bo2_d);
#pragma unroll
            for (int p = 0; p < 12; p++) acc[p] = b2;
#pragma unroll 4
            for (int c2 = 0; c2 < 16; c2++) {
                float2 w = w_o2P[c2 * 128 + tid];
                u64 wa = dup2(w.x), wb = dup2(w.y);
                const float4* sp = (const float4*)&actS[(2 * c2) * ACT_STRIDE];
                const float4* sq = (const float4*)&actS[(2 * c2 + 1) * ACT_STRIDE];
#pragma unroll
                for (int q = 0; q < 6; q++) {
                    float4 v = sp[q];
                    float4 u = sq[q];
                    acc[2 * q]     = fma2(wa, pack2(v.x, v.y), acc[2 * q]);
                    acc[2 * q + 1] = fma2(wa, pack2(v.z, v.w), acc[2 * q + 1]);
                    acc[2 * q]     = fma2(wb, pack2(u.x, u.y), acc[2 * q]);
                    acc[2 * q + 1] = fma2(wb, pack2(u.z, u.w), acc[2 * q + 1]);
                }
            }
            asm volatile("cp.async.wait_group 0;" ::: "memory");
            const float4* np = (const float4*)&nzS[tid * NZ_STRIDE];
            float* xp = &xs[tid * XS_STRIDE];
#pragma unroll
            for (int q = 0; q < 6; q++) {
                float4 nv = np[q];
                float4 xv = *(const float4*)&xp[4 * q];
                float2 e0 = unpk(acc[2 * q]);
                float2 e1 = unpk(acc[2 * q + 1]);
                float4 r;
                {
                    float x0 = (xv.x - s1m * e0.x) * isab;
                    x0 = fminf(fmaxf(x0, -1.f), 1.f);
                    r.x = fmaf(c0, x0, fmaf(cxt, xv.x, sg * nv.x));
                }
                {
                    float x0 = (xv.y - s1m * e0.y) * isab;
                    x0 = fminf(fmaxf(x0, -1.f), 1.f);
                    r.y = fmaf(c0, x0, fmaf(cxt, xv.y, sg * nv.y));
                }
                {
                    float x0 = (xv.z - s1m * e1.x) * isab;
                    x0 = fminf(fmaxf(x0, -1.f), 1.f);
                    r.z = fmaf(c0, x0, fmaf(cxt, xv.z, sg * nv.z));
                }
                {
                    float x0 = (xv.w - s1m * e1.y) * isab;
                    x0 = fminf(fmaxf(x0, -1.f), 1.f);
                    r.w = fmaf(c0, x0, fmaf(cxt, xv.w, sg * nv.w));
                }
                *(float4*)&xp[4 * q] = r;
            }
        }
        __syncthreads();
    }

    // ---- final: Gaussian -> Student-t4 marginal transform ----
    {
        int b = chain & 31;
        float lc = g_loc[b * 128 + tid];
        float scl = g_scale[b * 128 + tid];
        for (int hh = 0; hh < 24; hh++) {
            double z = (double)xs[tid * XS_STRIDE + hh];
            double u = 0.5 * erfc(-z * 0.70710678118654752440);
            u = fmin(fmax(u, 1e-6), 1.0 - 1e-6);
            double a = 4.0 * u * (1.0 - u);
            a = fmin(fmax(a, 1e-12), 1.0);
            double r = sqrt(a);
            double q = 2.0 * sqrt(fmax(cos(acos(r) / 3.0) / r - 1.0, 0.0));
            double sgn = (u >= 0.5) ? 1.0 : -1.0;
            out[((size_t)chain * 24 + hh) * 128 + tid] = (float)((double)lc + (double)scl * sgn * q);
        }
    }
}

extern "C" void kernel_launch(void* const* d_in, const int* in_sizes, int n_in,
                              void* d_out, int out_size) {
    const float* x_hist = (const float*)d_in[0];
    const float* z_init = (const float*)d_in[1];
    const float* noise = (const float*)d_in[2];
    const float* w_in = (const float*)d_in[3];
    const float* b_in = (const float*)d_in[4];
    const float* tw1 = (const float*)d_in[5];
    const float* tb1 = (const float*)d_in[6];
    const float* tw2 = (const float*)d_in[7];
    const float* tb2 = (const float*)d_in[8];
    const float* lwt = (const float*)d_in[9];
    const float* lbt = (const float*)d_in[10];
    const float* lwd = (const float*)d_in[11];
    const float* lbd = (const float*)d_in[12];
    const float* lwo = (const float*)d_in[13];
    const float* lbo = (const float*)d_in[14];
    const float* w_o1 = (const float*)d_in[15];
    const float* b_o1 = (const float*)d_in[16];
    const float* w_o2 = (const float*)d_in[17];
    const float* b_o2 = (const float*)d_in[18];
    float* out = (float*)d_out;

    k_prep<<<64, 256>>>(w_in, lwd, lwo, w_o1, w_o2);
    k_stats<<<32, 128>>>(x_hist);
    k_temb<<<50, 512>>>(tw1, tb1, tw2, tb2, lwt, lbt);
    k_main<<<512, 128>>>(z_init, noise, b_in, lbd, lbo, b_o1, b_o2, out);
}

// round 7
// speedup vs baseline: 1.2077x; 1.0033x over previous
#include <cuda_runtime.h>
#include <cuda_bf16.h>
#include <math.h>

// ---------------------------------------------------------------------------
// 512 independent diffusion chains; one persistent CTA (128 thr) per chain.
// Pair-packed weights (1 LDG.64 -> 2 fma2 streams), cp.async noise prefetch.
// ---------------------------------------------------------------------------

#define NSTEPS 50
#define HCP_STRIDE 90
#define ACT_STRIDE 28
#define XS_STRIDE  28
#define NZ_STRIDE  28
typedef unsigned long long u64;

// ---- device-global scratch (no allocations allowed) ----
__device__ float  g_loc[32 * 128];
__device__ float  g_scale[32 * 128];
__device__ float  g_cond[6 * NSTEPS * 32];   // [l][t][c]
__device__ float  g_coef[NSTEPS * 5];        // s1m, 1/sab, c0, cxt, sig
__device__ float2 w_inP[64 * 32];            // [d/2][c] -> (w[d], w[d+1])
__device__ float2 wdilP[6 * 32 * 3 * 32];    // [l][c][k][o] -> (gate, filt)
__device__ float2 woutP[6 * 32 * 32];        // [l][c][o] -> (res, skip)
__device__ float2 w_o1P[16 * 32];            // [c/2][o] -> (w[c], w[c+1]) /sqrt6
__device__ float2 w_o2P[16 * 128];           // [c/2][d] -> (w[c], w[c+1])

// ---- packed f32x2 helpers ----
__device__ __forceinline__ u64 fma2(u64 a, u64 b, u64 c) {
    u64 d; asm("fma.rn.f32x2 %0, %1, %2, %3;" : "=l"(d) : "l"(a), "l"(b), "l"(c)); return d;
}
__device__ __forceinline__ u64 add2(u64 a, u64 b) {
    u64 d; asm("add.rn.f32x2 %0, %1, %2;" : "=l"(d) : "l"(a), "l"(b)); return d;
}
__device__ __forceinline__ u64 mul2(u64 a, u64 b) {
    u64 d; asm("mul.rn.f32x2 %0, %1, %2;" : "=l"(d) : "l"(a), "l"(b)); return d;
}
__device__ __forceinline__ u64 pack2(float lo, float hi) {
    u64 r; asm("mov.b64 %0, {%1, %2};" : "=l"(r) : "f"(lo), "f"(hi)); return r;
}
__device__ __forceinline__ u64 dup2(float w) { return pack2(w, w); }
__device__ __forceinline__ float2 unpk(u64 a) {
    float2 v; asm("mov.b64 {%0, %1}, %2;" : "=f"(v.x), "=f"(v.y) : "l"(a)); return v;
}
__device__ __forceinline__ float sigm_f(float x) { return 1.0f / (1.0f + __expf(-x)); }
__device__ __forceinline__ float tanh_f(float x) { return 1.0f - 2.0f / (__expf(2.0f * x) + 1.0f); }
__device__ __forceinline__ void cpasync16(unsigned dst, const void* src) {
    asm volatile("cp.async.ca.shared.global [%0], [%1], 16;" :: "r"(dst), "l"(src));
}

// ---------------------------------------------------------------------------
// Setup: pair-packed weight transposes + DDPM schedule (double)
// ---------------------------------------------------------------------------
__global__ void k_prep(const float* __restrict__ w_in, const float* __restrict__ lwd,
                       const float* __restrict__ lwo, const float* __restrict__ w_o1,
                       const float* __restrict__ w_o2) {
    int i = blockIdx.x * blockDim.x + threadIdx.x;
    int nt = gridDim.x * blockDim.x;
    for (int idx = i; idx < 64 * 32; idx += nt) {
        int d2 = idx >> 5, c = idx & 31;
        w_inP[idx] = make_float2(w_in[c * 128 + 2 * d2], w_in[c * 128 + 2 * d2 + 1]);
    }
    for (int idx = i; idx < 6 * 32 * 3 * 32; idx += nt) {
        int o = idx & 31, r = idx >> 5;
        int k = r % 3, r2 = r / 3;
        int c = r2 & 31, l = r2 >> 5;
        wdilP[idx] = make_float2(lwd[((l * 64 + o) * 32 + c) * 3 + k],
                                 lwd[((l * 64 + 32 + o) * 32 + c) * 3 + k]);
    }
    for (int idx = i; idx < 6 * 32 * 32; idx += nt) {
        int o = idx & 31, r = idx >> 5;
        int c = r & 31, l = r >> 5;
        woutP[idx] = make_float2(lwo[(l * 64 + o) * 32 + c],
                                 lwo[(l * 64 + 32 + o) * 32 + c]);
    }
    for (int idx = i; idx < 16 * 32; idx += nt) {
        int o = idx & 31, c2 = idx >> 5;
        const float s = 0.40824829046386302f;  // 1/sqrt(6)
        w_o1P[idx] = make_float2(w_o1[o * 32 + 2 * c2] * s, w_o1[o * 32 + 2 * c2 + 1] * s);
    }
    for (int idx = i; idx < 16 * 128; idx += nt) {
        int d = idx & 127, c2 = idx >> 7;
        w_o2P[idx] = make_float2(w_o2[d * 32 + 2 * c2], w_o2[d * 32 + 2 * c2 + 1]);
    }
    if (i == 0) {
        double abar = 1.0;
        for (int t = 0; t < NSTEPS; t++) {
            double beta = 1e-4 + (double)t * (0.1 - 1e-4) / 49.0;
            double alpha = 1.0 - beta;
            double abar_prev = abar;
            abar *= alpha;
            double om = 1.0 - abar;
            g_coef[t * 5 + 0] = (float)sqrt(om);
            g_coef[t * 5 + 1] = (float)(1.0 / sqrt(abar));
            g_coef[t * 5 + 2] = (float)(beta * sqrt(abar_prev) / om);
            g_coef[t * 5 + 3] = (float)((1.0 - abar_prev) * sqrt(alpha) / om);
            double pv = beta * (1.0 - abar_prev) / om;
            g_coef[t * 5 + 4] = (t > 0) ? (float)sqrt(pv) : 0.0f;
        }
    }
}

// ---------------------------------------------------------------------------
// Setup: EWMA Student-t marginal fit. grid 32 (b) x 128 (d)
// ---------------------------------------------------------------------------
__global__ void k_stats(const float* __restrict__ x_hist) {
    int b = blockIdx.x, d = threadIdx.x;
    const float* xb = x_hist + (size_t)b * 192 * 128 + d;
    double s = 0.0;
    for (int t = 0; t < 192; t++) s += (double)xb[t * 128];
    float mean = (float)(s / 192.0);
    float c = xb[0] - mean;
    float v = c * c;
    for (int t = 1; t < 192; t++) {
        float cc = xb[t * 128] - mean;
        v = 0.94f * v + 0.06f * (cc * cc);
    }
    g_loc[b * 128 + d] = mean;
    g_scale[b * 128 + d] = fmaxf(sqrtf(v * 0.5f), 1e-5f);
}

// ---------------------------------------------------------------------------
// Setup: step embedding + per-layer cond. grid 50 (t) x 512 threads.
// ---------------------------------------------------------------------------
__global__ void k_temb(const float* __restrict__ w1, const float* __restrict__ b1,
                       const float* __restrict__ w2, const float* __restrict__ b2,
                       const float* __restrict__ wt, const float* __restrict__ bt) {
    __shared__ float pe[128], te1[512], te2[512];
    int t = blockIdx.x, tid = threadIdx.x;
    if (tid < 64) {
        float y = ((float)tid * 4.0f) / 63.0f;
        float p = (float)pow(10.0, (double)y);
        float e = (float)t * p;
        pe[tid] = (float)sin((double)e);
        pe[tid + 64] = (float)cos((double)e);
    }
    __syncthreads();
    {
        double a = (double)b1[tid];
        for (int j = 0; j < 128; j++) a += (double)pe[j] * (double)w1[j * 512 + tid];
        te1[tid] = (float)(a / (1.0 + exp(-a)));
    }
    __syncthreads();
    {
        double a = (double)b2[tid];
        for (int k = 0; k < 512; k++) a += (double)te1[k] * (double)w2[k * 512 + tid];
        te2[tid] = (float)(a / (1.0 + exp(-a)));
    }
    __syncthreads();
    if (tid < 192) {
        int l = tid >> 5, c = tid & 31;
        double a = (double)bt[l * 32 + c];
        for (int k = 0; k < 512; k++) a += (double)te2[k] * (double)wt[(l * 512 + k) * 32 + c];
        g_cond[(l * NSTEPS + t) * 32 + c] = (float)a;
    }
}

// ---------------------------------------------------------------------------
// Dilated conv, gate+filt per thread (o = lane, j0 = warp*6).
// Weights pair-packed: 3 LDG.64 per c-iter. Windows broadcast LDS.
// ---------------------------------------------------------------------------
template <int DIL>
__device__ __forceinline__ void conv_pair(const float2* __restrict__ wbase,
                                          const float* hcpS, int j0,
                                          u64 ag[3], u64 af[3]) {
#pragma unroll 4
    for (int c = 0; c < 32; c++) {
        const float2* wr = wbase + c * 96;
        float2 k0 = wr[0], k1 = wr[32], k2 = wr[64];
        u64 wg0 = dup2(k0.x), wf0 = dup2(k0.y);
        u64 wg1 = dup2(k1.x), wf1 = dup2(k1.y);
        u64 wg2 = dup2(k2.x), wf2 = dup2(k2.y);
        const float* hp = hcpS + c * HCP_STRIDE + 32 + j0;
        u64 m0 = *(const u64*)(hp), m1 = *(const u64*)(hp + 2), m2 = *(const u64*)(hp + 4);
        u64 lv0, lv1, lv2, rv0, rv1, rv2;
        if (DIL == 1) {
            float xm1 = hp[-1], x6 = hp[6];
            float2 f0 = unpk(m0), f1 = unpk(m1), f2 = unpk(m2);
            lv0 = pack2(xm1, f0.x); lv1 = pack2(f0.y, f1.x); lv2 = pack2(f1.y, f2.x);
            rv0 = lv1; rv1 = lv2; rv2 = pack2(f2.y, x6);
        } else if (DIL == 2) {
            lv0 = *(const u64*)(hp - 2); lv1 = m0; lv2 = m1;
            rv0 = m1; rv1 = m2; rv2 = *(const u64*)(hp + 6);
        } else if (DIL == 4) {
            lv0 = *(const u64*)(hp - 4); lv1 = *(const u64*)(hp - 2); lv2 = m0;
            rv0 = m2; rv1 = *(const u64*)(hp + 6); rv2 = *(const u64*)(hp + 8);
        } else {
            lv0 = *(const u64*)(hp - DIL); lv1 = *(const u64*)(hp - DIL + 2);
            lv2 = *(const u64*)(hp - DIL + 4);
            rv0 = *(const u64*)(hp + DIL); rv1 = *(const u64*)(hp + DIL + 2);
            rv2 = *(const u64*)(hp + DIL + 4);
        }
        ag[0] = fma2(wg0, lv0, ag[0]); ag[1] = fma2(wg0, lv1, ag[1]); ag[2] = fma2(wg0, lv2, ag[2]);
        ag[0] = fma2(wg1, m0,  ag[0]); ag[1] = fma2(wg1, m1,  ag[1]); ag[2] = fma2(wg1, m2,  ag[2]);
        ag[0] = fma2(wg2, rv0, ag[0]); ag[1] = fma2(wg2, rv1, ag[1]); ag[2] = fma2(wg2, rv2, ag[2]);
        af[0] = fma2(wf0, lv0, af[0]); af[1] = fma2(wf0, lv1, af[1]); af[2] = fma2(wf0, lv2, af[2]);
        af[0] = fma2(wf1, m0,  af[0]); af[1] = fma2(wf1, m1,  af[1]); af[2] = fma2(wf1, m2,  af[2]);
        af[0] = fma2(wf2, rv0, af[0]); af[1] = fma2(wf2, rv1, af[1]); af[2] = fma2(wf2, rv2, af[2]);
    }
}

// ---------------------------------------------------------------------------
// Main persistent kernel: grid 512 (chain) x 128 threads.
// ---------------------------------------------------------------------------
__global__ __launch_bounds__(128, 4) void k_main(
    const float* __restrict__ z_init, const float* __restrict__ noise,
    const float* __restrict__ b_in, const float* __restrict__ bdil,
    const float* __restrict__ bout, const float* __restrict__ b_o1,
    const float* __restrict__ b_o2, float* __restrict__ out) {
    __shared__ __align__(16) float xs[128 * XS_STRIDE];    // x state [d][j]
    __shared__ __align__(16) float hcp[32 * HCP_STRIDE];   // padded h+cond
    __shared__ __align__(16) float actS[32 * ACT_STRIDE];  // act / s
    __shared__ __align__(16) float skS[32 * 26];           // skip (written once)
    __shared__ __align__(16) float nzS[128 * NZ_STRIDE];   // prefetched noise

    const int tid = threadIdx.x, chain = blockIdx.x;
    const int lane = tid & 31, warp = tid >> 5;
    const int j0 = warp * 6;

    const unsigned nz_dst = (unsigned)__cvta_generic_to_shared(&nzS[tid * NZ_STRIDE]);

    // load z_init -> xs (stride 28, 16B-aligned rows)
    {
        const float4* zp = (const float4*)(z_init + (size_t)chain * 3072);
#pragma unroll
        for (int q = 0; q < 6; q++) {
            float4 v = zp[tid * 6 + q];
            *(float4*)&xs[tid * XS_STRIDE + 4 * q] = v;
        }
    }
    for (int i = tid; i < 32 * HCP_STRIDE; i += 128) hcp[i] = 0.f;
    __syncthreads();

    const float bin_l = b_in[lane];
    const float bo1_l = b_o1[lane];
    const float bo2_d = b_o2[tid];
    const u64 HALF2 = pack2(0.70710678118654752f, 0.70710678118654752f);

    u64 h[3], skp[3];

    for (int t = NSTEPS - 1; t >= 0; t--) {
        const float s1m = g_coef[t * 5 + 0], isab = g_coef[t * 5 + 1];
        const float c0 = g_coef[t * 5 + 2], cxt = g_coef[t * 5 + 3], sg = g_coef[t * 5 + 4];

        // ---- prefetch this step's noise into SMEM (used in phase G) ----
        {
            const float* nsrc = noise + ((size_t)(NSTEPS - 1 - t) * 512 + chain) * 3072 +
                                (size_t)tid * 24;
#pragma unroll
            for (int q = 0; q < 6; q++) cpasync16(nz_dst + 16 * q, nsrc + 4 * q);
            asm volatile("cp.async.commit_group;");
        }

        // ---- A: h = relu(W_in @ x + b); write hcp for layer 0 ----
        {
            u64 acc0 = dup2(bin_l), acc1 = acc0, acc2 = acc0;
#pragma unroll 4
            for (int d2 = 0; d2 < 64; d2++) {
                float2 w = w_inP[d2 * 32 + lane];
                u64 wx = dup2(w.x), wy = dup2(w.y);
                const float* xp = &xs[(2 * d2) * XS_STRIDE + j0];
                const float* xq = xp + XS_STRIDE;
                acc0 = fma2(wx, *(const u64*)(xp), acc0);
                acc1 = fma2(wx, *(const u64*)(xp + 2), acc1);
                acc2 = fma2(wx, *(const u64*)(xp + 4), acc2);
                acc0 = fma2(wy, *(const u64*)(xq), acc0);
                acc1 = fma2(wy, *(const u64*)(xq + 2), acc1);
                acc2 = fma2(wy, *(const u64*)(xq + 4), acc2);
            }
            float cnd = g_cond[t * 32 + lane];  // l = 0
            u64 cnd2 = dup2(cnd);
            u64 acc[3] = {acc0, acc1, acc2};
#pragma unroll
            for (int p = 0; p < 3; p++) {
                float2 v = unpk(acc[p]);
                h[p] = pack2(fmaxf(v.x, 0.f), fmaxf(v.y, 0.f));
                *(u64*)&hcp[lane * HCP_STRIDE + 32 + j0 + 2 * p] = add2(h[p], cnd2);
                skp[p] = 0ULL;
            }
        }
        __syncthreads();

        // ---- residual layers ----
        for (int l = 0; l < 6; l++) {
            // conv + gating fused
            {
                float bg = bdil[l * 64 + lane], bf = bdil[l * 64 + 32 + lane];
                u64 ag[3] = {dup2(bg), dup2(bg), dup2(bg)};
                u64 af[3] = {dup2(bf), dup2(bf), dup2(bf)};
                const float2* wbase = wdilP + l * (32 * 3 * 32) + lane;
                switch (l) {
                    case 0: conv_pair<1>(wbase, hcp, j0, ag, af); break;
                    case 1: conv_pair<2>(wbase, hcp, j0, ag, af); break;
                    case 2: conv_pair<4>(wbase, hcp, j0, ag, af); break;
                    case 3: conv_pair<8>(wbase, hcp, j0, ag, af); break;
                    case 4: conv_pair<16>(wbase, hcp, j0, ag, af); break;
                    default: conv_pair<32>(wbase, hcp, j0, ag, af); break;
                }
#pragma unroll
                for (int p = 0; p < 3; p++) {
                    float2 g = unpk(ag[p]), f = unpk(af[p]);
                    *(u64*)&actS[lane * ACT_STRIDE + j0 + 2 * p] =
                        pack2(tanh_f(f.x) * sigm_f(g.x), tanh_f(f.y) * sigm_f(g.y));
                }
            }
            __syncthreads();

            // E: res/skip GEMM + register h/skip updates, write next hcp
            {
                float br = bout[l * 64 + lane], bs = bout[l * 64 + 32 + lane];
                u64 ar[3] = {dup2(br), dup2(br), dup2(br)};
                u64 as_[3] = {dup2(bs), dup2(bs), dup2(bs)};
                const float2* wo = woutP + l * (32 * 32) + lane;
#pragma unroll 8
                for (int c = 0; c < 32; c++) {
                    float2 w = wo[c * 32];
                    u64 wr = dup2(w.x), ws = dup2(w.y);
                    const float* ap = &actS[c * ACT_STRIDE + j0];
#pragma unroll
                    for (int p = 0; p < 3; p++) {
                        u64 a = *(const u64*)(ap + 2 * p);
                        ar[p] = fma2(wr, a, ar[p]);
                        as_[p] = fma2(ws, a, as_[p]);
                    }
                }
                if (l < 5) {
                    float cn = g_cond[((l + 1) * NSTEPS + t) * 32 + lane];
                    u64 cn2 = dup2(cn);
#pragma unroll
                    for (int p = 0; p < 3; p++) {
                        h[p] = mul2(add2(h[p], ar[p]), HALF2);
                        skp[p] = add2(skp[p], as_[p]);
                        *(u64*)&hcp[lane * HCP_STRIDE + 32 + j0 + 2 * p] = add2(h[p], cn2);
                    }
                } else {
#pragma unroll
                    for (int p = 0; p < 3; p++) {
                        skp[p] = add2(skp[p], as_[p]);
                        *(u64*)&skS[lane * 26 + j0 + 2 * p] = skp[p];
                    }
                }
            }
            __syncthreads();
        }

        // ---- F: s = relu(W_o1 @ skip/sqrt6 + b) -> actS ----
        {
            u64 sa[3] = {dup2(bo1_l), dup2(bo1_l), dup2(bo1_l)};
#pragma unroll 8
            for (int c2 = 0; c2 < 16; c2++) {
                float2 w = w_o1P[c2 * 32 + lane];
                u64 wx = dup2(w.x), wy = dup2(w.y);
                const float* sp = &skS[(2 * c2) * 26 + j0];
                const float* sq = sp + 26;
                sa[0] = fma2(wx, *(const u64*)(sp), sa[0]);
                sa[1] = fma2(wx, *(const u64*)(sp + 2), sa[1]);
                sa[2] = fma2(wx, *(const u64*)(sp + 4), sa[2]);
                sa[0] = fma2(wy, *(const u64*)(sq), sa[0]);
                sa[1] = fma2(wy, *(const u64*)(sq + 2), sa[1]);
                sa[2] = fma2(wy, *(const u64*)(sq + 4), sa[2]);
            }
#pragma unroll
            for (int p = 0; p < 3; p++) {
                float2 v = unpk(sa[p]);
                *(u64*)&actS[lane * ACT_STRIDE + j0 + 2 * p] = pack2(fmaxf(v.x, 0.f), fmaxf(v.y, 0.f));
            }
        }
        __syncthreads();

        // ---- G: eps row d = tid, all 24 j; DDPM update of xs ----
        {
            u64 acc[12];
            u64 b2 = dup2(bo2_d);
#pragma unroll
            for (int p = 0; p < 12; p++) acc[p] = b2;
#pragma unroll 4
            for (int c2 = 0; c2 < 16; c2++) {
                float2 w = w_o2P[c2 * 128 + tid];
                u64 wa = dup2(w.x), wb = dup2(w.y);
                const float4* sp = (const float4*)&actS[(2 * c2) * ACT_STRIDE];
                const float4* sq = (const float4*)&actS[(2 * c2 + 1) * ACT_STRIDE];
#pragma unroll
                for (int q = 0; q < 6; q++) {
                    float4 v = sp[q];
                    float4 u = sq[q];
                    acc[2 * q]     = fma2(wa, pack2(v.x, v.y), acc[2 * q]);
                    acc[2 * q + 1] = fma2(wa, pack2(v.z, v.w), acc[2 * q + 1]);
                    acc[2 * q]     = fma2(wb, pack2(u.x, u.y), acc[2 * q]);
                    acc[2 * q + 1] = fma2(wb, pack2(u.z, u.w), acc[2 * q + 1]);
                }
            }
            asm volatile("cp.async.wait_group 0;" ::: "memory");
            const float4* np = (const float4*)&nzS[tid * NZ_STRIDE];
            float* xp = &xs[tid * XS_STRIDE];
#pragma unroll
            for (int q = 0; q < 6; q++) {
                float4 nv = np[q];
                float4 xv = *(const float4*)&xp[4 * q];
                float2 e0 = unpk(acc[2 * q]);
                float2 e1 = unpk(acc[2 * q + 1]);
                float4 r;
                {
                    float x0 = (xv.x - s1m * e0.x) * isab;
                    x0 = fminf(fmaxf(x0, -1.f), 1.f);
                    r.x = fmaf(c0, x0, fmaf(cxt, xv.x, sg * nv.x));
                }
                {
                    float x0 = (xv.y - s1m * e0.y) * isab;
                    x0 = fminf(fmaxf(x0, -1.f), 1.f);
                    r.y = fmaf(c0, x0, fmaf(cxt, xv.y, sg * nv.y));
                }
                {
                    float x0 = (xv.z - s1m * e1.x) * isab;
                    x0 = fminf(fmaxf(x0, -1.f), 1.f);
                    r.z = fmaf(c0, x0, fmaf(cxt, xv.z, sg * nv.z));
                }
                {
                    float x0 = (xv.w - s1m * e1.y) * isab;
                    x0 = fminf(fmaxf(x0, -1.f), 1.f);
                    r.w = fmaf(c0, x0, fmaf(cxt, xv.w, sg * nv.w));
                }
                *(float4*)&xp[4 * q] = r;
            }
        }
        __syncthreads();
    }

    // ---- final: Gaussian -> Student-t4 marginal transform ----
    {
        int b = chain & 31;
        float lc = g_loc[b * 128 + tid];
        float scl = g_scale[b * 128 + tid];
        for (int hh = 0; hh < 24; hh++) {
            double z = (double)xs[tid * XS_STRIDE + hh];
            double u = 0.5 * erfc(-z * 0.70710678118654752440);
            u = fmin(fmax(u, 1e-6), 1.0 - 1e-6);
            double a = 4.0 * u * (1.0 - u);
            a = fmin(fmax(a, 1e-12), 1.0);
            double r = sqrt(a);
            double q = 2.0 * sqrt(fmax(cos(acos(r) / 3.0) / r - 1.0, 0.0));
            double sgn = (u >= 0.5) ? 1.0 : -1.0;
            out[((size_t)chain * 24 + hh) * 128 + tid] = (float)((double)lc + (double)scl * sgn * q);
        }
    }
}

extern "C" void kernel_launch(void* const* d_in, const int* in_sizes, int n_in,
                              void* d_out, int out_size) {
    const float* x_hist = (const float*)d_in[0];
    const float* z_init = (const float*)d_in[1];
    const float* noise = (const float*)d_in[2];
    const float* w_in = (const float*)d_in[3];
    const float* b_in = (const float*)d_in[4];
    const float* tw1 = (const float*)d_in[5];
    const float* tb1 = (const float*)d_in[6];
    const float* tw2 = (const float*)d_in[7];
    const float* tb2 = (const float*)d_in[8];
    const float* lwt = (const float*)d_in[9];
    const float* lbt = (const float*)d_in[10];
    const float* lwd = (const float*)d_in[11];
    const float* lbd = (const float*)d_in[12];
    const float* lwo = (const float*)d_in[13];
    const float* lbo = (const float*)d_in[14];
    const float* w_o1 = (const float*)d_in[15];
    const float* b_o1 = (const float*)d_in[16];
    const float* w_o2 = (const float*)d_in[17];
    const float* b_o2 = (const float*)d_in[18];
    float* out = (float*)d_out;

    k_prep<<<64, 256>>>(w_in, lwd, lwo, w_o1, w_o2);
    k_stats<<<32, 128>>>(x_hist);
    k_temb<<<50, 512>>>(tw1, tb1, tw2, tb2, lwt, lbt);
    k_main<<<512, 128>>>(z_init, noise, b_in, lbd, lbo, b_o1, b_o2, out);
}

// round 8
// speedup vs baseline: 1.7282x; 1.4310x over previous
#include <cuda_runtime.h>
#include <cuda_fp16.h>
#include <math.h>

#define NSTEPS 50
#define HT 40          // halves per hT row
#define ACT_S 28
#define YB_S 26
typedef unsigned long long u64;
typedef unsigned u32;

__device__ float  g_loc[32 * 128];
__device__ float  g_scale[32 * 128];
__device__ float  g_cond[6 * NSTEPS * 32];
__device__ float  g_coef[NSTEPS * 5];
__device__ float2 w_inP[64 * 32];
__device__ float2 woutP[6 * 32 * 32];
__device__ float2 w_o1P[16 * 32];
__device__ float2 w_o2P[16 * 128];
__device__ uint4  g_wA[6 * 3 * 2 * 2 * 4 * 32];  // ((((l*3+tp)*2+kt)*2+var)*4+mt)*32+lane

__device__ __forceinline__ u64 fma2(u64 a, u64 b, u64 c) {
    u64 d; asm("fma.rn.f32x2 %0, %1, %2, %3;" : "=l"(d) : "l"(a), "l"(b), "l"(c)); return d;
}
__device__ __forceinline__ u64 add2(u64 a, u64 b) {
    u64 d; asm("add.rn.f32x2 %0, %1, %2;" : "=l"(d) : "l"(a), "l"(b)); return d;
}
__device__ __forceinline__ u64 mul2(u64 a, u64 b) {
    u64 d; asm("mul.rn.f32x2 %0, %1, %2;" : "=l"(d) : "l"(a), "l"(b)); return d;
}
__device__ __forceinline__ u64 pack2(float lo, float hi) {
    u64 r; asm("mov.b64 %0, {%1, %2};" : "=l"(r) : "f"(lo), "f"(hi)); return r;
}
__device__ __forceinline__ u64 dup2(float w) { return pack2(w, w); }
__device__ __forceinline__ float2 unpk(u64 a) {
    float2 v; asm("mov.b64 {%0, %1}, %2;" : "=f"(v.x), "=f"(v.y) : "l"(a)); return v;
}
__device__ __forceinline__ float sigm_f(float x) { return 1.0f / (1.0f + __expf(-x)); }
__device__ __forceinline__ float tanh_f(float x) { return 1.0f - 2.0f / (__expf(2.0f * x) + 1.0f); }
__device__ __forceinline__ void cpasync16(unsigned dst, const void* src) {
    asm volatile("cp.async.ca.shared.global [%0], [%1], 16;" :: "r"(dst), "l"(src));
}
__device__ __forceinline__ void mma16816(float c[4], const uint4& a, u32 b0, u32 b1) {
    asm volatile("mma.sync.aligned.m16n8k16.row.col.f32.f16.f16.f32 "
                 "{%0,%1,%2,%3}, {%4,%5,%6,%7}, {%8,%9}, {%0,%1,%2,%3};"
                 : "+f"(c[0]), "+f"(c[1]), "+f"(c[2]), "+f"(c[3])
                 : "r"(a.x), "r"(a.y), "r"(a.z), "r"(a.w), "r"(b0), "r"(b1));
}
__device__ __forceinline__ void hsplit(__half* hb, __half* lb, int c, int j, float v) {
    __half h = __float2half_rn(v);
    hb[(32 + j) * HT + c] = h;
    lb[(32 + j) * HT + c] = __float2half_rn(v - __half2float(h));
}

__global__ void k_prep(const float* __restrict__ w_in, const float* __restrict__ lwd,
                       const float* __restrict__ lwo, const float* __restrict__ w_o1,
                       const float* __restrict__ w_o2) {
    int i = blockIdx.x * blockDim.x + threadIdx.x;
    int nt = gridDim.x * blockDim.x;
    for (int idx = i; idx < 64 * 32; idx += nt) {
        int d2 = idx >> 5, c = idx & 31;
        w_inP[idx] = make_float2(w_in[c * 128 + 2 * d2], w_in[c * 128 + 2 * d2 + 1]);
    }
    for (int idx = i; idx < 6 * 32 * 32; idx += nt) {
        int o = idx & 31, r = idx >> 5, c = r & 31, l = r >> 5;
        woutP[idx] = make_float2(lwo[(l * 64 + o) * 32 + c], lwo[(l * 64 + 32 + o) * 32 + c]);
    }
    for (int idx = i; idx < 16 * 32; idx += nt) {
        int o = idx & 31, c2 = idx >> 5;
        const float s = 0.40824829046386302f;
        w_o1P[idx] = make_float2(w_o1[o * 32 + 2 * c2] * s, w_o1[o * 32 + 2 * c2 + 1] * s);
    }
    for (int idx = i; idx < 16 * 128; idx += nt) {
        int d = idx & 127, c2 = idx >> 7;
        w_o2P[idx] = make_float2(w_o2[d * 32 + 2 * c2], w_o2[d * 32 + 2 * c2 + 1]);
    }
    for (int idx = i; idx < 6 * 3 * 2 * 2 * 4 * 32; idx += nt) {
        int lane = idx & 31, r = idx >> 5;
        int mt = r & 3; r >>= 2;
        int var = r & 1; r >>= 1;
        int kt = r & 1; r >>= 1;
        int tp = r % 3, l = r / 3;
        int g = mt * 16 + (lane >> 2);
        int cb = kt * 16 + 2 * (lane & 3);
        auto enc = [&](int o, int c) -> u32 {
            float w0 = lwd[((l * 64 + o) * 32 + c) * 3 + tp];
            float w1 = lwd[((l * 64 + o) * 32 + c + 1) * 3 + tp];
            __half h0 = __float2half_rn(w0), h1 = __float2half_rn(w1);
            if (var) {
                h0 = __float2half_rn(w0 - __half2float(h0));
                h1 = __float2half_rn(w1 - __half2float(h1));
            }
            return (u32)__half_as_ushort(h0) | ((u32)__half_as_ushort(h1) << 16);
        };
        uint4 v;
        v.x = enc(g, cb); v.y = enc(g + 8, cb);
        v.z = enc(g, cb + 8); v.w = enc(g + 8, cb + 8);
        g_wA[idx] = v;
    }
    if (i == 0) {
        double abar = 1.0;
        for (int t = 0; t < NSTEPS; t++) {
            double beta = 1e-4 + (double)t * (0.1 - 1e-4) / 49.0;
            double alpha = 1.0 - beta, abp = abar;
            abar *= alpha;
            double om = 1.0 - abar;
            g_coef[t * 5 + 0] = (float)sqrt(om);
            g_coef[t * 5 + 1] = (float)(1.0 / sqrt(abar));
            g_coef[t * 5 + 2] = (float)(beta * sqrt(abp) / om);
            g_coef[t * 5 + 3] = (float)((1.0 - abp) * sqrt(alpha) / om);
            double pv = beta * (1.0 - abp) / om;
            g_coef[t * 5 + 4] = (t > 0) ? (float)sqrt(pv) : 0.0f;
        }
    }
}

__global__ void k_stats(const float* __restrict__ x_hist) {
    int b = blockIdx.x, d = threadIdx.x;
    const float* xb = x_hist + (size_t)b * 192 * 128 + d;
    double s = 0.0;
    for (int t = 0; t < 192; t++) s += (double)xb[t * 128];
    float mean = (float)(s / 192.0);
    float c = xb[0] - mean;
    float v = c * c;
    for (int t = 1; t < 192; t++) {
        float cc = xb[t * 128] - mean;
        v = 0.94f * v + 0.06f * (cc * cc);
    }
    g_loc[b * 128 + d] = mean;
    g_scale[b * 128 + d] = fmaxf(sqrtf(v * 0.5f), 1e-5f);
}

__global__ void k_temb(const float* __restrict__ w1, const float* __restrict__ b1,
                       const float* __restrict__ w2, const float* __restrict__ b2,
                       const float* __restrict__ wt, const float* __restrict__ bt) {
    __shared__ float pe[128], te1[512], te2[512];
    int t = blockIdx.x, tid = threadIdx.x;
    if (tid < 64) {
        float y = ((float)tid * 4.0f) / 63.0f;
        float p = (float)pow(10.0, (double)y);
        float e = (float)t * p;
        pe[tid] = (float)sin((double)e);
        pe[tid + 64] = (float)cos((double)e);
    }
    __syncthreads();
    {
        double a = (double)b1[tid];
        for (int j = 0; j < 128; j++) a += (double)pe[j] * (double)w1[j * 512 + tid];
        te1[tid] = (float)(a / (1.0 + exp(-a)));
    }
    __syncthreads();
    {
        double a = (double)b2[tid];
        for (int k = 0; k < 512; k++) a += (double)te1[k] * (double)w2[k * 512 + tid];
        te2[tid] = (float)(a / (1.0 + exp(-a)));
    }
    __syncthreads();
    if (tid < 192) {
        int l = tid >> 5, c = tid & 31;
        double a = (double)bt[l * 32 + c];
        for (int k = 0; k < 512; k++) a += (double)te2[k] * (double)wt[(l * 512 + k) * 32 + c];
        g_cond[(l * NSTEPS + t) * 32 + c] = (float)a;
    }
}

// conv via MMA: warp mt covers o rows [mt*16, mt*16+16); writes yb[64][YB_S]
template <int DIL>
__device__ __forceinline__ void conv_mma(const __half* hT_hi, const __half* hT_lo,
                                         float* yb, const float* __restrict__ bdil,
                                         int l, int mt, int lane) {
    const int frow = lane >> 2, fcol = 2 * (lane & 3);
    float acc[3][4];
    float b0v = bdil[l * 64 + mt * 16 + frow];
    float b8v = bdil[l * 64 + mt * 16 + frow + 8];
#pragma unroll
    for (int n = 0; n < 3; n++) { acc[n][0] = b0v; acc[n][1] = b0v; acc[n][2] = b8v; acc[n][3] = b8v; }
#pragma unroll
    for (int tp = 0; tp < 3; tp++) {
#pragma unroll
        for (int kt = 0; kt < 2; kt++) {
            int base = ((((l * 3 + tp) * 2 + kt) * 2) * 4 + mt) * 32 + lane;
            uint4 Ah = g_wA[base];
            uint4 Al = g_wA[base + 128];
#pragma unroll
            for (int n = 0; n < 3; n++) {
                int row = 32 + n * 8 + frow + (tp - 1) * DIL;
                int coff = row * HT + kt * 16 + fcol;
                u32 bh0 = *(const u32*)&hT_hi[coff];
                u32 bh1 = *(const u32*)&hT_hi[coff + 8];
                u32 bl0 = *(const u32*)&hT_lo[coff];
                u32 bl1 = *(const u32*)&hT_lo[coff + 8];
                mma16816(acc[n], Ah, bh0, bh1);
                mma16816(acc[n], Ah, bl0, bl1);
                mma16816(acc[n], Al, bh0, bh1);
            }
        }
    }
    int o = mt * 16 + frow;
#pragma unroll
    for (int n = 0; n < 3; n++) {
        int j = n * 8 + fcol;
        *(float2*)&yb[o * YB_S + j] = make_float2(acc[n][0], acc[n][1]);
        *(float2*)&yb[(o + 8) * YB_S + j] = make_float2(acc[n][2], acc[n][3]);
    }
}

__global__ __launch_bounds__(128, 4) void k_main(
    const float* __restrict__ z_init, const float* __restrict__ noise,
    const float* __restrict__ b_in, const float* __restrict__ bdil,
    const float* __restrict__ bout, const float* __restrict__ b_o1,
    const float* __restrict__ b_o2, float* __restrict__ out) {
    extern __shared__ __align__(16) char dyn[];
    __half* hT_hi = (__half*)dyn;                      // 88*HT = 7040B
    __half* hT_lo = (__half*)(dyn + 7040);             // 7040B
    float* xs   = (float*)(dyn + 14080);               // 128*24
    float* nzS  = (float*)(dyn + 14080 + 12288);       // 128*24
    float* yb   = (float*)(dyn + 38656);               // 64*26
    float* actS = (float*)(dyn + 45312);               // 32*28
    float* skS  = (float*)(dyn + 48896);               // 32*26 -> total 52224

    const int tid = threadIdx.x, chain = blockIdx.x;
    const int lane = tid & 31, warp = tid >> 5;
    const int j0 = warp * 6;
    const unsigned nz_dst = (unsigned)__cvta_generic_to_shared(&nzS[tid * 24]);

    {
        const float4* zp = (const float4*)(z_init + (size_t)chain * 3072);
#pragma unroll
        for (int q = 0; q < 6; q++) *(float4*)&xs[tid * 24 + 4 * q] = zp[tid * 6 + q];
    }
    for (int i = tid; i < 88 * HT / 2; i += 128) { ((u32*)hT_hi)[i] = 0u; ((u32*)hT_lo)[i] = 0u; }
    __syncthreads();

    const float bin_l = b_in[lane];
    const float bo1_l = b_o1[lane];
    const float bo2_d = b_o2[tid];
    const u64 HALF2 = pack2(0.70710678118654752f, 0.70710678118654752f);
    u64 h[3], skp[3];

    for (int t = NSTEPS - 1; t >= 0; t--) {
        const float s1m = g_coef[t * 5], isab = g_coef[t * 5 + 1];
        const float c0 = g_coef[t * 5 + 2], cxt = g_coef[t * 5 + 3], sg = g_coef[t * 5 + 4];
        {
            const float* nsrc = noise + ((size_t)(NSTEPS - 1 - t) * 512 + chain) * 3072 + (size_t)tid * 24;
#pragma unroll
            for (int q = 0; q < 6; q++) cpasync16(nz_dst + 16 * q, nsrc + 4 * q);
            asm volatile("cp.async.commit_group;");
        }
        // A: h = relu(W_in @ x + b) -> hT (fp16 split)
        {
            u64 acc0 = dup2(bin_l), acc1 = acc0, acc2 = acc0;
#pragma unroll 4
            for (int d2 = 0; d2 < 64; d2++) {
                float2 w = w_inP[d2 * 32 + lane];
                u64 wx = dup2(w.x), wy = dup2(w.y);
                const float* xp = &xs[(2 * d2) * 24 + j0];
                acc0 = fma2(wx, *(const u64*)(xp), acc0);
                acc1 = fma2(wx, *(const u64*)(xp + 2), acc1);
                acc2 = fma2(wx, *(const u64*)(xp + 4), acc2);
                acc0 = fma2(wy, *(const u64*)(xp + 24), acc0);
                acc1 = fma2(wy, *(const u64*)(xp + 26), acc1);
                acc2 = fma2(wy, *(const u64*)(xp + 28), acc2);
            }
            float cnd = g_cond[t * 32 + lane];
            u64 cnd2 = dup2(cnd);
            u64 acc[3] = {acc0, acc1, acc2};
#pragma unroll
            for (int p = 0; p < 3; p++) {
                float2 v = unpk(acc[p]);
                h[p] = pack2(fmaxf(v.x, 0.f), fmaxf(v.y, 0.f));
                float2 hc = unpk(add2(h[p], cnd2));
                hsplit(hT_hi, hT_lo, lane, j0 + 2 * p, hc.x);
                hsplit(hT_hi, hT_lo, lane, j0 + 2 * p + 1, hc.y);
                skp[p] = 0ULL;
            }
        }
        __syncthreads();

        for (int l = 0; l < 6; l++) {
            switch (l) {
                case 0: conv_mma<1>(hT_hi, hT_lo, yb, bdil, l, warp, lane); break;
                case 1: conv_mma<2>(hT_hi, hT_lo, yb, bdil, l, warp, lane); break;
                case 2: conv_mma<4>(hT_hi, hT_lo, yb, bdil, l, warp, lane); break;
                case 3: conv_mma<8>(hT_hi, hT_lo, yb, bdil, l, warp, lane); break;
                case 4: conv_mma<16>(hT_hi, hT_lo, yb, bdil, l, warp, lane); break;
                default: conv_mma<32>(hT_hi, hT_lo, yb, bdil, l, warp, lane); break;
            }
            __syncthreads();
            // gating: act = tanh(filt)*sigmoid(gate)
#pragma unroll
            for (int p = 0; p < 3; p++) {
                float2 g = *(const float2*)&yb[lane * YB_S + j0 + 2 * p];
                float2 f = *(const float2*)&yb[(lane + 32) * YB_S + j0 + 2 * p];
                *(u64*)&actS[lane * ACT_S + j0 + 2 * p] =
                    pack2(tanh_f(f.x) * sigm_f(g.x), tanh_f(f.y) * sigm_f(g.y));
            }
            __syncthreads();
            // E: res/skip GEMM; update h/skip regs; write next hT
            {
                float br = bout[l * 64 + lane], bs = bout[l * 64 + 32 + lane];
                u64 ar[3] = {dup2(br), dup2(br), dup2(br)};
                u64 as_[3] = {dup2(bs), dup2(bs), dup2(bs)};
                const float2* wo = woutP + l * (32 * 32) + lane;
#pragma unroll 8
                for (int c = 0; c < 32; c++) {
                    float2 w = wo[c * 32];
                    u64 wr = dup2(w.x), ws = dup2(w.y);
                    const float* ap = &actS[c * ACT_S + j0];
#pragma unroll
                    for (int p = 0; p < 3; p++) {
                        u64 a = *(const u64*)(ap + 2 * p);
                        ar[p] = fma2(wr, a, ar[p]);
                        as_[p] = fma2(ws, a, as_[p]);
                    }
                }
                if (l < 5) {
                    float cn = g_cond[((l + 1) * NSTEPS + t) * 32 + lane];
                    u64 cn2 = dup2(cn);
#pragma unroll
                    for (int p = 0; p < 3; p++) {
                        h[p] = mul2(add2(h[p], ar[p]), HALF2);
                        skp[p] = add2(skp[p], as_[p]);
                        float2 hc = unpk(add2(h[p], cn2));
                        hsplit(hT_hi, hT_lo, lane, j0 + 2 * p, hc.x);
                        hsplit(hT_hi, hT_lo, lane, j0 + 2 * p + 1, hc.y);
                    }
                } else {
#pragma unroll
                    for (int p = 0; p < 3; p++) {
                        skp[p] = add2(skp[p], as_[p]);
                        *(u64*)&skS[lane * 26 + j0 + 2 * p] = skp[p];
                    }
                }
            }
            __syncthreads();
        }
        // F
        {
            u64 sa[3] = {dup2(bo1_l), dup2(bo1_l), dup2(bo1_l)};
#pragma unroll 8
            for (int c2 = 0; c2 < 16; c2++) {
                float2 w = w_o1P[c2 * 32 + lane];
                u64 wx = dup2(w.x), wy = dup2(w.y);
                const float* sp = &skS[(2 * c2) * 26 + j0];
                sa[0] = fma2(wx, *(const u64*)(sp), sa[0]);
                sa[1] = fma2(wx, *(const u64*)(sp + 2), sa[1]);
                sa[2] = fma2(wx, *(const u64*)(sp + 4), sa[2]);
                sa[0] = fma2(wy, *(const u64*)(sp + 26), sa[0]);
                sa[1] = fma2(wy, *(const u64*)(sp + 28), sa[1]);
                sa[2] = fma2(wy, *(const u64*)(sp + 30), sa[2]);
            }
#pragma unroll
            for (int p = 0; p < 3; p++) {
                float2 v = unpk(sa[p]);
                *(u64*)&actS[lane * ACT_S + j0 + 2 * p] = pack2(fmaxf(v.x, 0.f), fmaxf(v.y, 0.f));
            }
        }
        __syncthreads();
        // G: eps row d = tid; DDPM update
        {
            u64 acc[12];
            u64 b2 = dup2(bo2_d);
#pragma unroll
            for (int p = 0; p < 12; p++) acc[p] = b2;
#pragma unroll 4
            for (int c2 = 0; c2 < 16; c2++) {
                float2 w = w_o2P[c2 * 128 + tid];
                u64 wa = dup2(w.x), wb = dup2(w.y);
                const float4* sp = (const float4*)&actS[(2 * c2) * ACT_S];
                const float4* sq = (const float4*)&actS[(2 * c2 + 1) * ACT_S];
#pragma unroll
                for (int q = 0; q < 6; q++) {
                    float4 v = sp[q], u = sq[q];
                    acc[2 * q]     = fma2(wa, pack2(v.x, v.y), acc[2 * q]);
                    acc[2 * q + 1] = fma2(wa, pack2(v.z, v.w), acc[2 * q + 1]);
                    acc[2 * q]     = fma2(wb, pack2(u.x, u.y), acc[2 * q]);
                    acc[2 * q + 1] = fma2(wb, pack2(u.z, u.w), acc[2 * q + 1]);
                }
            }
            asm volatile("cp.async.wait_group 0;" ::: "memory");
            const float4* np = (const float4*)&nzS[tid * 24];
            float* xp = &xs[tid * 24];
#pragma unroll
            for (int q = 0; q < 6; q++) {
                float4 nv = np[q];
                float4 xv = *(const float4*)&xp[4 * q];
                float2 e0 = unpk(acc[2 * q]), e1 = unpk(acc[2 * q + 1]);
                float4 r;
                float x0;
                x0 = fminf(fmaxf((xv.x - s1m * e0.x) * isab, -1.f), 1.f);
                r.x = fmaf(c0, x0, fmaf(cxt, xv.x, sg * nv.x));
                x0 = fminf(fmaxf((xv.y - s1m * e0.y) * isab, -1.f), 1.f);
                r.y = fmaf(c0, x0, fmaf(cxt, xv.y, sg * nv.y));
                x0 = fminf(fmaxf((xv.z - s1m * e1.x) * isab, -1.f), 1.f);
                r.z = fmaf(c0, x0, fmaf(cxt, xv.z, sg * nv.z));
                x0 = fminf(fmaxf((xv.w - s1m * e1.y) * isab, -1.f), 1.f);
                r.w = fmaf(c0, x0, fmaf(cxt, xv.w, sg * nv.w));
                *(float4*)&xp[4 * q] = r;
            }
        }
        __syncthreads();
    }
    {
        int b = chain & 31;
        float lc = g_loc[b * 128 + tid];
        float scl = g_scale[b * 128 + tid];
        for (int hh = 0; hh < 24; hh++) {
            double z = (double)xs[tid * 24 + hh];
            double u = 0.5 * erfc(-z * 0.70710678118654752440);
            u = fmin(fmax(u, 1e-6), 1.0 - 1e-6);
            double a = 4.0 * u * (1.0 - u);
            a = fmin(fmax(a, 1e-12), 1.0);
            double r = sqrt(a);
            double q = 2.0 * sqrt(fmax(cos(acos(r) / 3.0) / r - 1.0, 0.0));
            double sgn = (u >= 0.5) ? 1.0 : -1.0;
            out[((size_t)chain * 24 + hh) * 128 + tid] = (float)((double)lc + (double)scl * sgn * q);
        }
    }
}

extern "C" void kernel_launch(void* const* d_in, const int* in_sizes, int n_in,
                              void* d_out, int out_size) {
    const float* x_hist = (const float*)d_in[0];
    const float* z_init = (const float*)d_in[1];
    const float* noise = (const float*)d_in[2];
    const float* w_in = (const float*)d_in[3];
    const float* b_in = (const float*)d_in[4];
    const float* tw1 = (const float*)d_in[5];
    const float* tb1 = (const float*)d_in[6];
    const float* tw2 = (const float*)d_in[7];
    const float* tb2 = (const float*)d_in[8];
    const float* lwt = (const float*)d_in[9];
    const float* lbt = (const float*)d_in[10];
    const float* lwd = (const float*)d_in[11];
    const float* lbd = (const float*)d_in[12];
    const float* lwo = (const float*)d_in[13];
    const float* lbo = (const float*)d_in[14];
    const float* w_o1 = (const float*)d_in[15];
    const float* b_o1 = (const float*)d_in[16];
    const float* w_o2 = (const float*)d_in[17];
    const float* b_o2 = (const float*)d_in[18];
    float* out = (float*)d_out;

    const int SMEM = 52224;
    cudaFuncSetAttribute(k_main, cudaFuncAttributeMaxDynamicSharedMemorySize, SMEM);
    k_prep<<<64, 256>>>(w_in, lwd, lwo, w_o1, w_o2);
    k_stats<<<32, 128>>>(x_hist);
    k_temb<<<50, 512>>>(tw1, tb1, tw2, tb2, lwt, lbt);
    k_main<<<512, 128, SMEM>>>(z_init, noise, b_in, lbd, lbo, b_o1, b_o2, out);
}

// round 9
// speedup vs baseline: 2.1989x; 1.2723x over previous
#include <cuda_runtime.h>
#include <cuda_fp16.h>
#include <math.h>

#define NSTEPS 50
#define HT 40
#define ACT_S 28
typedef unsigned long long u64;
typedef unsigned u32;

__device__ float  g_loc[32 * 128];
__device__ float  g_scale[32 * 128];
__device__ float  g_cond[6 * NSTEPS * 32];
__device__ float  g_coef[NSTEPS * 5];
__device__ float2 w_inP[64 * 32];
__device__ float2 w_o1P[16 * 32];
__device__ float2 w_o2P[16 * 128];
__device__ uint4  g_wA[6 * 3 * 2 * 2 * 4 * 32];  // ((((l*3+tp)*2+kt)*2+var)*4+mt)*32+lane
__device__ uint4  g_wE[6 * 2 * 2 * 4 * 32];      // (((l*2+kt)*2+var)*4+mt)*32+lane

__device__ __forceinline__ u64 fma2(u64 a, u64 b, u64 c) {
    u64 d; asm("fma.rn.f32x2 %0, %1, %2, %3;" : "=l"(d) : "l"(a), "l"(b), "l"(c)); return d;
}
__device__ __forceinline__ u64 add2(u64 a, u64 b) {
    u64 d; asm("add.rn.f32x2 %0, %1, %2;" : "=l"(d) : "l"(a), "l"(b)); return d;
}
__device__ __forceinline__ u64 pack2(float lo, float hi) {
    u64 r; asm("mov.b64 %0, {%1, %2};" : "=l"(r) : "f"(lo), "f"(hi)); return r;
}
__device__ __forceinline__ u64 dup2(float w) { return pack2(w, w); }
__device__ __forceinline__ float2 unpk(u64 a) {
    float2 v; asm("mov.b64 {%0, %1}, %2;" : "=f"(v.x), "=f"(v.y) : "l"(a)); return v;
}
__device__ __forceinline__ float sigm_f(float x) { return 1.0f / (1.0f + __expf(-x)); }
__device__ __forceinline__ float tanh_f(float x) { return 1.0f - 2.0f / (__expf(2.0f * x) + 1.0f); }
__device__ __forceinline__ void cpasync16(unsigned dst, const void* src) {
    asm volatile("cp.async.ca.shared.global [%0], [%1], 16;" :: "r"(dst), "l"(src));
}
__device__ __forceinline__ void mma16816(float c[4], const uint4& a, u32 b0, u32 b1) {
    asm volatile("mma.sync.aligned.m16n8k16.row.col.f32.f16.f16.f32 "
                 "{%0,%1,%2,%3}, {%4,%5,%6,%7}, {%8,%9}, {%0,%1,%2,%3};"
                 : "+f"(c[0]), "+f"(c[1]), "+f"(c[2]), "+f"(c[3])
                 : "r"(a.x), "r"(a.y), "r"(a.z), "r"(a.w), "r"(b0), "r"(b1));
}
__device__ __forceinline__ void hsplit(__half* hb, __half* lb, int c, int j, float v) {
    __half h = __float2half_rn(v);
    hb[(32 + j) * HT + c] = h;
    lb[(32 + j) * HT + c] = __float2half_rn(v - __half2float(h));
}
__device__ __forceinline__ void asplit(__half* hb, __half* lb, int c, int j, float v) {
    __half h = __float2half_rn(v);
    hb[j * HT + c] = h;
    lb[j * HT + c] = __float2half_rn(v - __half2float(h));
}

__global__ void k_prep(const float* __restrict__ w_in, const float* __restrict__ lwd,
                       const float* __restrict__ lwo, const float* __restrict__ w_o1,
                       const float* __restrict__ w_o2) {
    int i = blockIdx.x * blockDim.x + threadIdx.x;
    int nt = gridDim.x * blockDim.x;
    for (int idx = i; idx < 64 * 32; idx += nt) {
        int d2 = idx >> 5, c = idx & 31;
        w_inP[idx] = make_float2(w_in[c * 128 + 2 * d2], w_in[c * 128 + 2 * d2 + 1]);
    }
    for (int idx = i; idx < 16 * 32; idx += nt) {
        int o = idx & 31, c2 = idx >> 5;
        const float s = 0.40824829046386302f;
        w_o1P[idx] = make_float2(w_o1[o * 32 + 2 * c2] * s, w_o1[o * 32 + 2 * c2 + 1] * s);
    }
    for (int idx = i; idx < 16 * 128; idx += nt) {
        int d = idx & 127, c2 = idx >> 7;
        w_o2P[idx] = make_float2(w_o2[d * 32 + 2 * c2], w_o2[d * 32 + 2 * c2 + 1]);
    }
    for (int idx = i; idx < 6 * 3 * 2 * 2 * 4 * 32; idx += nt) {
        int lane = idx & 31, r = idx >> 5;
        int mt = r & 3; r >>= 2;
        int var = r & 1; r >>= 1;
        int kt = r & 1; r >>= 1;
        int tp = r % 3, l = r / 3;
        int og = 8 * mt + (lane >> 2);        // gate row (tile rows 0-7)
        int of = 32 + 8 * mt + (lane >> 2);   // filt row (tile rows 8-15)
        int cb = kt * 16 + 2 * (lane & 3);
        auto enc = [&](int o, int c) -> u32 {
            float w0 = lwd[((l * 64 + o) * 32 + c) * 3 + tp];
            float w1 = lwd[((l * 64 + o) * 32 + c + 1) * 3 + tp];
            __half h0 = __float2half_rn(w0), h1 = __float2half_rn(w1);
            if (var) {
                h0 = __float2half_rn(w0 - __half2float(h0));
                h1 = __float2half_rn(w1 - __half2float(h1));
            }
            return (u32)__half_as_ushort(h0) | ((u32)__half_as_ushort(h1) << 16);
        };
        uint4 v;
        v.x = enc(og, cb); v.y = enc(of, cb);
        v.z = enc(og, cb + 8); v.w = enc(of, cb + 8);
        g_wA[idx] = v;
    }
    for (int idx = i; idx < 6 * 2 * 2 * 4 * 32; idx += nt) {
        int lane = idx & 31, r = idx >> 5;
        int mt = r & 3; r >>= 2;
        int var = r & 1; r >>= 1;
        int kt = r & 1; r >>= 1;
        int l = r;
        int o = 16 * mt + (lane >> 2);
        int cb = kt * 16 + 2 * (lane & 3);
        auto encE = [&](int oo, int c) -> u32 {
            float w0 = lwo[(l * 64 + oo) * 32 + c];
            float w1 = lwo[(l * 64 + oo) * 32 + c + 1];
            __half h0 = __float2half_rn(w0), h1 = __float2half_rn(w1);
            if (var) {
                h0 = __float2half_rn(w0 - __half2float(h0));
                h1 = __float2half_rn(w1 - __half2float(h1));
            }
            return (u32)__half_as_ushort(h0) | ((u32)__half_as_ushort(h1) << 16);
        };
        uint4 v;
        v.x = encE(o, cb); v.y = encE(o + 8, cb);
        v.z = encE(o, cb + 8); v.w = encE(o + 8, cb + 8);
        g_wE[idx] = v;
    }
    if (i == 0) {
        double abar = 1.0;
        for (int t = 0; t < NSTEPS; t++) {
            double beta = 1e-4 + (double)t * (0.1 - 1e-4) / 49.0;
            double alpha = 1.0 - beta, abp = abar;
            abar *= alpha;
            double om = 1.0 - abar;
            g_coef[t * 5 + 0] = (float)sqrt(om);
            g_coef[t * 5 + 1] = (float)(1.0 / sqrt(abar));
            g_coef[t * 5 + 2] = (float)(beta * sqrt(abp) / om);
            g_coef[t * 5 + 3] = (float)((1.0 - abp) * sqrt(alpha) / om);
            double pv = beta * (1.0 - abp) / om;
            g_coef[t * 5 + 4] = (t > 0) ? (float)sqrt(pv) : 0.0f;
        }
    }
}

__global__ void k_stats(const float* __restrict__ x_hist) {
    int b = blockIdx.x, d = threadIdx.x;
    const float* xb = x_hist + (size_t)b * 192 * 128 + d;
    double s = 0.0;
    for (int t = 0; t < 192; t++) s += (double)xb[t * 128];
    float mean = (float)(s / 192.0);
    float c = xb[0] - mean;
    float v = c * c;
    for (int t = 1; t < 192; t++) {
        float cc = xb[t * 128] - mean;
        v = 0.94f * v + 0.06f * (cc * cc);
    }
    g_loc[b * 128 + d] = mean;
    g_scale[b * 128 + d] = fmaxf(sqrtf(v * 0.5f), 1e-5f);
}

__global__ void k_temb(const float* __restrict__ w1, const float* __restrict__ b1,
                       const float* __restrict__ w2, const float* __restrict__ b2,
                       const float* __restrict__ wt, const float* __restrict__ bt) {
    __shared__ float pe[128], te1[512], te2[512];
    int t = blockIdx.x, tid = threadIdx.x;
    if (tid < 64) {
        float y = ((float)tid * 4.0f) / 63.0f;
        float p = (float)pow(10.0, (double)y);
        float e = (float)t * p;
        pe[tid] = (float)sin((double)e);
        pe[tid + 64] = (float)cos((double)e);
    }
    __syncthreads();
    {
        double a = (double)b1[tid];
        for (int j = 0; j < 128; j++) a += (double)pe[j] * (double)w1[j * 512 + tid];
        te1[tid] = (float)(a / (1.0 + exp(-a)));
    }
    __syncthreads();
    {
        double a = (double)b2[tid];
        for (int k = 0; k < 512; k++) a += (double)te1[k] * (double)w2[k * 512 + tid];
        te2[tid] = (float)(a / (1.0 + exp(-a)));
    }
    __syncthreads();
    if (tid < 192) {
        int l = tid >> 5, c = tid & 31;
        double a = (double)bt[l * 32 + c];
        for (int k = 0; k < 512; k++) a += (double)te2[k] * (double)wt[(l * 512 + k) * 32 + c];
        g_cond[(l * NSTEPS + t) * 32 + c] = (float)a;
    }
}

// conv + gating fused: warp w covers gate o=8w..8w+7 and filt (same o) in one tile.
template <int DIL>
__device__ __forceinline__ void conv_mma(const __half* hT_hi, const __half* hT_lo,
                                         __half* aT_hi, __half* aT_lo,
                                         const float* __restrict__ bdil,
                                         int l, int w, int lane) {
    const int frow = lane >> 2, fcol = 2 * (lane & 3);
    float bg = bdil[l * 64 + 8 * w + frow], bf = bdil[l * 64 + 32 + 8 * w + frow];
    float acc[3][4];
#pragma unroll
    for (int n = 0; n < 3; n++) { acc[n][0] = bg; acc[n][1] = bg; acc[n][2] = bf; acc[n][3] = bf; }
#pragma unroll
    for (int tp = 0; tp < 3; tp++)
#pragma unroll
        for (int kt = 0; kt < 2; kt++) {
            int base = ((((l * 3 + tp) * 2 + kt) * 2) * 4 + w) * 32 + lane;
            uint4 Ah = g_wA[base], Al = g_wA[base + 128];
#pragma unroll
            for (int n = 0; n < 3; n++) {
                int row = 32 + n * 8 + frow + (tp - 1) * DIL;
                int coff = row * HT + kt * 16 + fcol;
                u32 bh0 = *(const u32*)&hT_hi[coff], bh1 = *(const u32*)&hT_hi[coff + 8];
                u32 bl0 = *(const u32*)&hT_lo[coff], bl1 = *(const u32*)&hT_lo[coff + 8];
                mma16816(acc[n], Ah, bh0, bh1);
                mma16816(acc[n], Ah, bl0, bl1);
                mma16816(acc[n], Al, bh0, bh1);
            }
        }
    int o = 8 * w + frow;
#pragma unroll
    for (int n = 0; n < 3; n++) {
        int j = n * 8 + fcol;
        asplit(aT_hi, aT_lo, o, j, tanh_f(acc[n][2]) * sigm_f(acc[n][0]));
        asplit(aT_hi, aT_lo, o, j + 1, tanh_f(acc[n][3]) * sigm_f(acc[n][1]));
    }
}

__global__ __launch_bounds__(128, 4) void k_main(
    const float* __restrict__ z_init, const float* __restrict__ noise,
    const float* __restrict__ b_in, const float* __restrict__ bdil,
    const float* __restrict__ bout, const float* __restrict__ b_o1,
    const float* __restrict__ b_o2, float* __restrict__ out) {
    extern __shared__ __align__(16) char dyn[];
    __half* hT_hi = (__half*)dyn;                  // 88*40*2 = 7040
    __half* hT_lo = (__half*)(dyn + 7040);
    __half* aT_hi = (__half*)(dyn + 14080);        // 24*40*2 = 1920
    __half* aT_lo = (__half*)(dyn + 16000);
    float* xs   = (float*)(dyn + 17920);           // 128*24*4 = 12288
    float* nzS  = (float*)(dyn + 30208);           // 12288
    float* skS  = (float*)(dyn + 42496);           // 32*26*4 = 3328
    float* hF   = (float*)(dyn + 45824);           // 32*28*4 = 3584 (union with actS)
    float* actS = hF;                              // total 49408

    const int tid = threadIdx.x, chain = blockIdx.x;
    const int lane = tid & 31, warp = tid >> 5;
    const int j0 = warp * 6;
    const int frow = lane >> 2, fcol = 2 * (lane & 3);
    const unsigned nz_dst = (unsigned)__cvta_generic_to_shared(&nzS[tid * 24]);

    {
        const float4* zp = (const float4*)(z_init + (size_t)chain * 3072);
#pragma unroll
        for (int q = 0; q < 6; q++) *(float4*)&xs[tid * 24 + 4 * q] = zp[tid * 6 + q];
    }
    for (int i = tid; i < 88 * HT / 2; i += 128) { ((u32*)hT_hi)[i] = 0u; ((u32*)hT_lo)[i] = 0u; }
    __syncthreads();

    const float bin_l = b_in[lane];
    const float bo1_l = b_o1[lane];
    const float bo2_d = b_o2[tid];
    float fR[3][4];  // res warps: h fragments; skip warps: skip accumulator

    for (int t = NSTEPS - 1; t >= 0; t--) {
        const float s1m = g_coef[t * 5], isab = g_coef[t * 5 + 1];
        const float c0 = g_coef[t * 5 + 2], cxt = g_coef[t * 5 + 3], sg = g_coef[t * 5 + 4];
        {
            const float* nsrc = noise + ((size_t)(NSTEPS - 1 - t) * 512 + chain) * 3072 + (size_t)tid * 24;
#pragma unroll
            for (int q = 0; q < 6; q++) cpasync16(nz_dst + 16 * q, nsrc + 4 * q);
            asm volatile("cp.async.commit_group;");
        }
        // A: h = relu(W_in @ x + b) -> hT split (+cond) and hF f32
        {
            u64 acc0 = dup2(bin_l), acc1 = acc0, acc2 = acc0;
#pragma unroll 4
            for (int d2 = 0; d2 < 64; d2++) {
                float2 w = w_inP[d2 * 32 + lane];
                u64 wx = dup2(w.x), wy = dup2(w.y);
                const float* xp = &xs[(2 * d2) * 24 + j0];
                acc0 = fma2(wx, *(const u64*)(xp), acc0);
                acc1 = fma2(wx, *(const u64*)(xp + 2), acc1);
                acc2 = fma2(wx, *(const u64*)(xp + 4), acc2);
                acc0 = fma2(wy, *(const u64*)(xp + 24), acc0);
                acc1 = fma2(wy, *(const u64*)(xp + 26), acc1);
                acc2 = fma2(wy, *(const u64*)(xp + 28), acc2);
            }
            float cnd = g_cond[t * 32 + lane];
            u64 acc[3] = {acc0, acc1, acc2};
#pragma unroll
            for (int p = 0; p < 3; p++) {
                float2 v = unpk(acc[p]);
                float h0 = fmaxf(v.x, 0.f), h1 = fmaxf(v.y, 0.f);
                *(float2*)&hF[lane * ACT_S + j0 + 2 * p] = make_float2(h0, h1);
                hsplit(hT_hi, hT_lo, lane, j0 + 2 * p, h0 + cnd);
                hsplit(hT_hi, hT_lo, lane, j0 + 2 * p + 1, h1 + cnd);
            }
        }
        __syncthreads();
        // init fragment state: res warps load h from hF, skip warps zero
        if (warp < 2) {
            int c = 16 * warp + frow;
#pragma unroll
            for (int n = 0; n < 3; n++) {
                float2 a = *(const float2*)&hF[c * ACT_S + n * 8 + fcol];
                float2 b = *(const float2*)&hF[(c + 8) * ACT_S + n * 8 + fcol];
                fR[n][0] = a.x; fR[n][1] = a.y; fR[n][2] = b.x; fR[n][3] = b.y;
            }
        } else {
#pragma unroll
            for (int n = 0; n < 3; n++) { fR[n][0] = 0.f; fR[n][1] = 0.f; fR[n][2] = 0.f; fR[n][3] = 0.f; }
        }

        for (int l = 0; l < 6; l++) {
            switch (l) {
                case 0: conv_mma<1>(hT_hi, hT_lo, aT_hi, aT_lo, bdil, l, warp, lane); break;
                case 1: conv_mma<2>(hT_hi, hT_lo, aT_hi, aT_lo, bdil, l, warp, lane); break;
                case 2: conv_mma<4>(hT_hi, hT_lo, aT_hi, aT_lo, bdil, l, warp, lane); break;
                case 3: conv_mma<8>(hT_hi, hT_lo, aT_hi, aT_lo, bdil, l, warp, lane); break;
                case 4: conv_mma<16>(hT_hi, hT_lo, aT_hi, aT_lo, bdil, l, warp, lane); break;
                default: conv_mma<32>(hT_hi, hT_lo, aT_hi, aT_lo, bdil, l, warp, lane); break;
            }
            __syncthreads();
            // E: res/skip via MMA, state in fragments
            {
                bool resw = (warp < 2);
                if (resw ? (l < 5) : true) {
                    int c = resw ? 16 * warp + frow : 16 * (warp - 2) + frow;
                    int ob = resw ? c : 32 + c;
                    float b0 = bout[l * 64 + ob], b8 = bout[l * 64 + ob + 8];
                    float acc[3][4];
#pragma unroll
                    for (int n = 0; n < 3; n++) { acc[n][0] = b0; acc[n][1] = b0; acc[n][2] = b8; acc[n][3] = b8; }
#pragma unroll
                    for (int kt = 0; kt < 2; kt++) {
                        int base = (((l * 2 + kt) * 2) * 4 + warp) * 32 + lane;
                        uint4 Ah = g_wE[base], Al = g_wE[base + 128];
#pragma unroll
                        for (int n = 0; n < 3; n++) {
                            int coff = (n * 8 + frow) * HT + kt * 16 + fcol;
                            u32 bh0 = *(const u32*)&aT_hi[coff], bh1 = *(const u32*)&aT_hi[coff + 8];
                            u32 bl0 = *(const u32*)&aT_lo[coff], bl1 = *(const u32*)&aT_lo[coff + 8];
                            mma16816(acc[n], Ah, bh0, bh1);
                            mma16816(acc[n], Ah, bl0, bl1);
                            mma16816(acc[n], Al, bh0, bh1);
                        }
                    }
                    if (resw) {
                        float cn0 = g_cond[((l + 1) * NSTEPS + t) * 32 + c];
                        float cn8 = g_cond[((l + 1) * NSTEPS + t) * 32 + c + 8];
#pragma unroll
                        for (int n = 0; n < 3; n++) {
                            int j = n * 8 + fcol;
#pragma unroll
                            for (int q = 0; q < 4; q++)
                                fR[n][q] = (fR[n][q] + acc[n][q]) * 0.70710678118654752f;
                            hsplit(hT_hi, hT_lo, c, j, fR[n][0] + cn0);
                            hsplit(hT_hi, hT_lo, c, j + 1, fR[n][1] + cn0);
                            hsplit(hT_hi, hT_lo, c + 8, j, fR[n][2] + cn8);
                            hsplit(hT_hi, hT_lo, c + 8, j + 1, fR[n][3] + cn8);
                        }
                    } else {
#pragma unroll
                        for (int n = 0; n < 3; n++) {
#pragma unroll
                            for (int q = 0; q < 4; q++) fR[n][q] += acc[n][q];
                        }
                        if (l == 5) {
#pragma unroll
                            for (int n = 0; n < 3; n++) {
                                int j = n * 8 + fcol;
                                skS[c * 26 + j] = fR[n][0];
                                skS[c * 26 + j + 1] = fR[n][1];
                                skS[(c + 8) * 26 + j] = fR[n][2];
                                skS[(c + 8) * 26 + j + 1] = fR[n][3];
                            }
                        }
                    }
                }
            }
            __syncthreads();
        }
        // F: s = relu(W_o1 @ skip/sqrt6 + b) -> actS
        {
            u64 sa[3] = {dup2(bo1_l), dup2(bo1_l), dup2(bo1_l)};
#pragma unroll 8
            for (int c2 = 0; c2 < 16; c2++) {
                float2 w = w_o1P[c2 * 32 + lane];
                u64 wx = dup2(w.x), wy = dup2(w.y);
                const float* sp = &skS[(2 * c2) * 26 + j0];
                sa[0] = fma2(wx, *(const u64*)(sp), sa[0]);
                sa[1] = fma2(wx, *(const u64*)(sp + 2), sa[1]);
                sa[2] = fma2(wx, *(const u64*)(sp + 4), sa[2]);
                sa[0] = fma2(wy, *(const u64*)(sp + 26), sa[0]);
                sa[1] = fma2(wy, *(const u64*)(sp + 28), sa[1]);
                sa[2] = fma2(wy, *(const u64*)(sp + 30), sa[2]);
            }
#pragma unroll
            for (int p = 0; p < 3; p++) {
                float2 v = unpk(sa[p]);
                *(u64*)&actS[lane * ACT_S + j0 + 2 * p] = pack2(fmaxf(v.x, 0.f), fmaxf(v.y, 0.f));
            }
        }
        __syncthreads();
        // G: eps row d = tid; DDPM update
        {
            u64 acc[12];
            u64 b2 = dup2(bo2_d);
#pragma unroll
            for (int p = 0; p < 12; p++) acc[p] = b2;
#pragma unroll 4
            for (int c2 = 0; c2 < 16; c2++) {
                float2 w = w_o2P[c2 * 128 + tid];
                u64 wa = dup2(w.x), wb = dup2(w.y);
                const float4* sp = (const float4*)&actS[(2 * c2) * ACT_S];
                const float4* sq = (const float4*)&actS[(2 * c2 + 1) * ACT_S];
#pragma unroll
                for (int q = 0; q < 6; q++) {
                    float4 v = sp[q], u = sq[q];
                    acc[2 * q]     = fma2(wa, pack2(v.x, v.y), acc[2 * q]);
                    acc[2 * q + 1] = fma2(wa, pack2(v.z, v.w), acc[2 * q + 1]);
                    acc[2 * q]     = fma2(wb, pack2(u.x, u.y), acc[2 * q]);
                    acc[2 * q + 1] = fma2(wb, pack2(u.z, u.w), acc[2 * q + 1]);
                }
            }
            asm volatile("cp.async.wait_group 0;" ::: "memory");
            const float4* np = (const float4*)&nzS[tid * 24];
            float* xp = &xs[tid * 24];
#pragma unroll
            for (int q = 0; q < 6; q++) {
                float4 nv = np[q];
                float4 xv = *(const float4*)&xp[4 * q];
                float2 e0 = unpk(acc[2 * q]), e1 = unpk(acc[2 * q + 1]);
                float4 r;
                float x0;
                x0 = fminf(fmaxf((xv.x - s1m * e0.x) * isab, -1.f), 1.f);
                r.x = fmaf(c0, x0, fmaf(cxt, xv.x, sg * nv.x));
                x0 = fminf(fmaxf((xv.y - s1m * e0.y) * isab, -1.f), 1.f);
                r.y = fmaf(c0, x0, fmaf(cxt, xv.y, sg * nv.y));
                x0 = fminf(fmaxf((xv.z - s1m * e1.x) * isab, -1.f), 1.f);
                r.z = fmaf(c0, x0, fmaf(cxt, xv.z, sg * nv.z));
                x0 = fminf(fmaxf((xv.w - s1m * e1.y) * isab, -1.f), 1.f);
                r.w = fmaf(c0, x0, fmaf(cxt, xv.w, sg * nv.w));
                *(float4*)&xp[4 * q] = r;
            }
        }
        __syncthreads();
    }
    {
        int b = chain & 31;
        float lc = g_loc[b * 128 + tid];
        float scl = g_scale[b * 128 + tid];
        for (int hh = 0; hh < 24; hh++) {
            double z = (double)xs[tid * 24 + hh];
            double u = 0.5 * erfc(-z * 0.70710678118654752440);
            u = fmin(fmax(u, 1e-6), 1.0 - 1e-6);
            double a = 4.0 * u * (1.0 - u);
            a = fmin(fmax(a, 1e-12), 1.0);
            double r = sqrt(a);
            double q = 2.0 * sqrt(fmax(cos(acos(r) / 3.0) / r - 1.0, 0.0));
            double sgn = (u >= 0.5) ? 1.0 : -1.0;
            out[((size_t)chain * 24 + hh) * 128 + tid] = (float)((double)lc + (double)scl * sgn * q);
        }
    }
}

extern "C" void kernel_launch(void* const* d_in, const int* in_sizes, int n_in,
                              void* d_out, int out_size) {
    const float* x_hist = (const float*)d_in[0];
    const float* z_init = (const float*)d_in[1];
    const float* noise = (const float*)d_in[2];
    const float* w_in = (const float*)d_in[3];
    const float* b_in = (const float*)d_in[4];
    const float* tw1 = (const float*)d_in[5];
    const float* tb1 = (const float*)d_in[6];
    const float* tw2 = (const float*)d_in[7];
    const float* tb2 = (const float*)d_in[8];
    const float* lwt = (const float*)d_in[9];
    const float* lbt = (const float*)d_in[10];
    const float* lwd = (const float*)d_in[11];
    const float* lbd = (const float*)d_in[12];
    const float* lwo = (const float*)d_in[13];
    const float* lbo = (const float*)d_in[14];
    const float* w_o1 = (const float*)d_in[15];
    const float* b_o1 = (const float*)d_in[16];
    const float* w_o2 = (const float*)d_in[17];
    const float* b_o2 = (const float*)d_in[18];
    float* out = (float*)d_out;

    const int SMEM = 49408;
    cudaFuncSetAttribute(k_main, cudaFuncAttributeMaxDynamicSharedMemorySize, SMEM);
    k_prep<<<64, 256>>>(w_in, lwd, lwo, w_o1, w_o2);
    k_stats<<<32, 128>>>(x_hist);
    k_temb<<<50, 512>>>(tw1, tb1, tw2, tb2, lwt, lbt);
    k_main<<<512, 128, SMEM>>>(z_init, noise, b_in, lbd, lbo, b_o1, b_o2, out);
}

// round 10
// speedup vs baseline: 2.7451x; 1.2484x over previous
#include <cuda_runtime.h>
#include <cuda_fp16.h>
#include <math.h>

#define NSTEPS 50
#define HT 40
#define XT 136
typedef unsigned u32;

__device__ float g_loc[4096], g_scale[4096];
__device__ float g_cond[6 * NSTEPS * 32], g_coef[NSTEPS * 5];
__device__ uint4 g_wA[6 * 3 * 2 * 2 * 4 * 32];
__device__ uint4 g_wE[6 * 2 * 2 * 4 * 32];
__device__ uint4 g_wIn[8 * 2 * 2 * 32];
__device__ uint4 g_wF[2 * 2 * 2 * 32];
__device__ uint4 g_wG[2 * 2 * 8 * 32];

__device__ __forceinline__ float sigm_f(float x) { return 1.0f / (1.0f + __expf(-x)); }
__device__ __forceinline__ float tanh_f(float x) { return 1.0f - 2.0f / (__expf(2.0f * x) + 1.0f); }
__device__ __forceinline__ void cpasync16(unsigned dst, const void* src) {
    asm volatile("cp.async.ca.shared.global [%0], [%1], 16;" :: "r"(dst), "l"(src));
}
__device__ __forceinline__ void mma16816(float c[4], const uint4& a, u32 b0, u32 b1) {
    asm volatile("mma.sync.aligned.m16n8k16.row.col.f32.f16.f16.f32 "
                 "{%0,%1,%2,%3}, {%4,%5,%6,%7}, {%8,%9}, {%0,%1,%2,%3};"
                 : "+f"(c[0]), "+f"(c[1]), "+f"(c[2]), "+f"(c[3])
                 : "r"(a.x), "r"(a.y), "r"(a.z), "r"(a.w), "r"(b0), "r"(b1));
}
__device__ __forceinline__ void wsplit(__half* hb, __half* lb, int idx, float v) {
    __half h = __float2half_rn(v);
    hb[idx] = h;
    lb[idx] = __float2half_rn(v - __half2float(h));
}

__device__ __forceinline__ u32 encpair(float w0, float w1, int var) {
    __half h0 = __float2half_rn(w0), h1 = __float2half_rn(w1);
    if (var) {
        h0 = __float2half_rn(w0 - __half2float(h0));
        h1 = __float2half_rn(w1 - __half2float(h1));
    }
    return (u32)__half_as_ushort(h0) | ((u32)__half_as_ushort(h1) << 16);
}

__global__ void k_prep(const float* __restrict__ w_in, const float* __restrict__ lwd,
                       const float* __restrict__ lwo, const float* __restrict__ w_o1,
                       const float* __restrict__ w_o2) {
    int i = blockIdx.x * blockDim.x + threadIdx.x;
    int nt = gridDim.x * blockDim.x;
    for (int idx = i; idx < 6 * 3 * 2 * 2 * 4 * 32; idx += nt) {
        int lane = idx & 31, r = idx >> 5;
        int mt = r & 3; r >>= 2;
        int var = r & 1; r >>= 1;
        int kt = r & 1; r >>= 1;
        int tp = r % 3, l = r / 3;
        int og = 8 * mt + (lane >> 2);
        int of = 32 + 8 * mt + (lane >> 2);
        int cb = kt * 16 + 2 * (lane & 3);
        auto w = [&](int o, int c) { return lwd[((l * 64 + o) * 32 + c) * 3 + tp]; };
        uint4 v;
        v.x = encpair(w(og, cb), w(og, cb + 1), var);
        v.y = encpair(w(of, cb), w(of, cb + 1), var);
        v.z = encpair(w(og, cb + 8), w(og, cb + 9), var);
        v.w = encpair(w(of, cb + 8), w(of, cb + 9), var);
        g_wA[idx] = v;
    }
    for (int idx = i; idx < 6 * 2 * 2 * 4 * 32; idx += nt) {
        int lane = idx & 31, r = idx >> 5;
        int mt = r & 3; r >>= 2;
        int var = r & 1; r >>= 1;
        int kt = r & 1; r >>= 1;
        int l = r;
        int o = 16 * mt + (lane >> 2);
        int cb = kt * 16 + 2 * (lane & 3);
        auto w = [&](int oo, int c) { return lwo[(l * 64 + oo) * 32 + c]; };
        uint4 v;
        v.x = encpair(w(o, cb), w(o, cb + 1), var);
        v.y = encpair(w(o + 8, cb), w(o + 8, cb + 1), var);
        v.z = encpair(w(o, cb + 8), w(o, cb + 9), var);
        v.w = encpair(w(o + 8, cb + 8), w(o + 8, cb + 9), var);
        g_wE[idx] = v;
    }
    for (int idx = i; idx < 8 * 2 * 2 * 32; idx += nt) {
        int lane = idx & 31, r = idx >> 5;
        int mt = r & 1; r >>= 1;
        int var = r & 1; r >>= 1;
        int kc = r;
        int o = 16 * mt + (lane >> 2);
        int cb = kc * 16 + 2 * (lane & 3);
        auto w = [&](int oo, int d) { return w_in[oo * 128 + d]; };
        uint4 v;
        v.x = encpair(w(o, cb), w(o, cb + 1), var);
        v.y = encpair(w(o + 8, cb), w(o + 8, cb + 1), var);
        v.z = encpair(w(o, cb + 8), w(o, cb + 9), var);
        v.w = encpair(w(o + 8, cb + 8), w(o + 8, cb + 9), var);
        g_wIn[idx] = v;
    }
    for (int idx = i; idx < 2 * 2 * 2 * 32; idx += nt) {
        int lane = idx & 31, r = idx >> 5;
        int mt = r & 1; r >>= 1;
        int var = r & 1; r >>= 1;
        int kt = r;
        int o = 16 * mt + (lane >> 2);
        int cb = kt * 16 + 2 * (lane & 3);
        const float s = 0.40824829046386302f;
        auto w = [&](int oo, int c) { return w_o1[oo * 32 + c] * s; };
        uint4 v;
        v.x = encpair(w(o, cb), w(o, cb + 1), var);
        v.y = encpair(w(o + 8, cb), w(o + 8, cb + 1), var);
        v.z = encpair(w(o, cb + 8), w(o, cb + 9), var);
        v.w = encpair(w(o + 8, cb + 8), w(o + 8, cb + 9), var);
        g_wF[idx] = v;
    }
    for (int idx = i; idx < 2 * 2 * 8 * 32; idx += nt) {
        int lane = idx & 31, r = idx >> 5;
        int mt8 = r & 7; r >>= 3;
        int var = r & 1; r >>= 1;
        int kt = r;
        int o = 16 * mt8 + (lane >> 2);
        int cb = kt * 16 + 2 * (lane & 3);
        auto w = [&](int oo, int c) { return w_o2[oo * 32 + c]; };
        uint4 v;
        v.x = encpair(w(o, cb), w(o, cb + 1), var);
        v.y = encpair(w(o + 8, cb), w(o + 8, cb + 1), var);
        v.z = encpair(w(o, cb + 8), w(o, cb + 9), var);
        v.w = encpair(w(o + 8, cb + 8), w(o + 8, cb + 9), var);
        g_wG[idx] = v;
    }
    if (i == 0) {
        double abar = 1.0;
        for (int t = 0; t < NSTEPS; t++) {
            double beta = 1e-4 + (double)t * (0.1 - 1e-4) / 49.0;
            double alpha = 1.0 - beta, abp = abar;
            abar *= alpha;
            double om = 1.0 - abar;
            g_coef[t * 5 + 0] = (float)sqrt(om);
            g_coef[t * 5 + 1] = (float)(1.0 / sqrt(abar));
            g_coef[t * 5 + 2] = (float)(beta * sqrt(abp) / om);
            g_coef[t * 5 + 3] = (float)((1.0 - abp) * sqrt(alpha) / om);
            double pv = beta * (1.0 - abp) / om;
            g_coef[t * 5 + 4] = (t > 0) ? (float)sqrt(pv) : 0.0f;
        }
    }
}

__global__ void k_stats(const float* __restrict__ x_hist) {
    int b = blockIdx.x, d = threadIdx.x;
    const float* xb = x_hist + (size_t)b * 192 * 128 + d;
    double s = 0.0;
    for (int t = 0; t < 192; t++) s += (double)xb[t * 128];
    float mean = (float)(s / 192.0);
    float c = xb[0] - mean;
    float v = c * c;
    for (int t = 1; t < 192; t++) {
        float cc = xb[t * 128] - mean;
        v = 0.94f * v + 0.06f * (cc * cc);
    }
    g_loc[b * 128 + d] = mean;
    g_scale[b * 128 + d] = fmaxf(sqrtf(v * 0.5f), 1e-5f);
}

__global__ void k_temb(const float* __restrict__ w1, const float* __restrict__ b1,
                       const float* __restrict__ w2, const float* __restrict__ b2,
                       const float* __restrict__ wt, const float* __restrict__ bt) {
    __shared__ float pe[128], te1[512], te2[512];
    int t = blockIdx.x, tid = threadIdx.x;
    if (tid < 64) {
        float y = ((float)tid * 4.0f) / 63.0f;
        float p = (float)pow(10.0, (double)y);
        float e = (float)t * p;
        pe[tid] = (float)sin((double)e);
        pe[tid + 64] = (float)cos((double)e);
    }
    __syncthreads();
    {
        double a = (double)b1[tid];
        for (int j = 0; j < 128; j++) a += (double)pe[j] * (double)w1[j * 512 + tid];
        te1[tid] = (float)(a / (1.0 + exp(-a)));
    }
    __syncthreads();
    {
        double a = (double)b2[tid];
        for (int k = 0; k < 512; k++) a += (double)te1[k] * (double)w2[k * 512 + tid];
        te2[tid] = (float)(a / (1.0 + exp(-a)));
    }
    __syncthreads();
    if (tid < 192) {
        int l = tid >> 5, c = tid & 31;
        double a = (double)bt[l * 32 + c];
        for (int k = 0; k < 512; k++) a += (double)te2[k] * (double)wt[(l * 512 + k) * 32 + c];
        g_cond[(l * NSTEPS + t) * 32 + c] = (float)a;
    }
}

template <int DIL>
__device__ __forceinline__ void conv_mma(const __half* hT_hi, const __half* hT_lo,
                                         __half* aT_hi, __half* aT_lo,
                                         const float* __restrict__ bdil,
                                         int l, int w, int lane) {
    const int frow = lane >> 2, fcol = 2 * (lane & 3);
    float bg = bdil[l * 64 + 8 * w + frow], bf = bdil[l * 64 + 32 + 8 * w + frow];
    float acc[3][4];
#pragma unroll
    for (int n = 0; n < 3; n++) { acc[n][0] = bg; acc[n][1] = bg; acc[n][2] = bf; acc[n][3] = bf; }
#pragma unroll
    for (int tp = 0; tp < 3; tp++)
#pragma unroll
        for (int kt = 0; kt < 2; kt++) {
            int base = ((((l * 3 + tp) * 2 + kt) * 2) * 4 + w) * 32 + lane;
            uint4 Ah = g_wA[base], Al = g_wA[base + 128];
#pragma unroll
            for (int n = 0; n < 3; n++) {
                int coff = (32 + n * 8 + frow + (tp - 1) * DIL) * HT + kt * 16 + fcol;
                u32 bh0 = *(const u32*)&hT_hi[coff], bh1 = *(const u32*)&hT_hi[coff + 8];
                u32 bl0 = *(const u32*)&hT_lo[coff], bl1 = *(const u32*)&hT_lo[coff + 8];
                mma16816(acc[n], Ah, bh0, bh1);
                mma16816(acc[n], Ah, bl0, bl1);
                mma16816(acc[n], Al, bh0, bh1);
            }
        }
    int o = 8 * w + frow;
#pragma unroll
    for (int n = 0; n < 3; n++) {
        int j = n * 8 + fcol;
        wsplit(aT_hi, aT_lo, j * HT + o, tanh_f(acc[n][2]) * sigm_f(acc[n][0]));
        wsplit(aT_hi, aT_lo, (j + 1) * HT + o, tanh_f(acc[n][3]) * sigm_f(acc[n][1]));
    }
}

__global__ __launch_bounds__(128, 4) void k_main(
    const float* __restrict__ z_init, const float* __restrict__ noise,
    const float* __restrict__ b_in, const float* __restrict__ bdil,
    const float* __restrict__ bout, const float* __restrict__ b_o1,
    const float* __restrict__ b_o2, float* __restrict__ out) {
    extern __shared__ __align__(16) char dyn[];
    __half* hT_hi = (__half*)dyn;                    // 88*40*2 = 7040
    __half* hT_lo = (__half*)(dyn + 7040);
    __half* aT_hi = (__half*)(dyn + 14080);          // 24*40*2 = 1920
    __half* aT_lo = (__half*)(dyn + 16000);
    __half* skT_hi = (__half*)(dyn + 17920);
    __half* skT_lo = (__half*)(dyn + 19840);
    __half* xT_hi = (__half*)(dyn + 21760);          // 24*136*2 = 6528
    __half* xT_lo = (__half*)(dyn + 28288);
    float* nzS = (float*)(dyn + 34816);              // 12288 -> 47104

    const int tid = threadIdx.x, chain = blockIdx.x;
    const int lane = tid & 31, warp = tid >> 5;
    const int frow = lane >> 2, fcol = 2 * (lane & 3);
    const unsigned nz_dst = (unsigned)__cvta_generic_to_shared(&nzS[tid * 24]);

    {
        const float4* zp = (const float4*)(z_init + (size_t)chain * 3072);
#pragma unroll
        for (int q = 0; q < 6; q++) {
            float4 v = zp[tid * 6 + q];
            int j = 4 * q;
            wsplit(xT_hi, xT_lo, j * XT + tid, v.x);
            wsplit(xT_hi, xT_lo, (j + 1) * XT + tid, v.y);
            wsplit(xT_hi, xT_lo, (j + 2) * XT + tid, v.z);
            wsplit(xT_hi, xT_lo, (j + 3) * XT + tid, v.w);
        }
    }
    for (int i = tid; i < 88 * HT / 2; i += 128) { ((u32*)hT_hi)[i] = 0u; ((u32*)hT_lo)[i] = 0u; }
    __syncthreads();

    float fR[3][4];

    for (int t = NSTEPS - 1; t >= 0; t--) {
        const float s1m = g_coef[t * 5], isab = g_coef[t * 5 + 1];
        const float c0 = g_coef[t * 5 + 2], cxt = g_coef[t * 5 + 3], sg = g_coef[t * 5 + 4];
        {
            const float* nsrc = noise + ((size_t)(NSTEPS - 1 - t) * 512 + chain) * 3072 + (size_t)tid * 24;
#pragma unroll
            for (int q = 0; q < 6; q++) cpasync16(nz_dst + 16 * q, nsrc + 4 * q);
            asm volatile("cp.async.commit_group;");
        }
        // A: h = relu(W_in @ x + b) via MMA, warps 0-1; fragments ARE res-warp h state
        if (warp < 2) {
            int c = 16 * warp + frow;
            float b0 = b_in[c], b8 = b_in[c + 8];
            float cn0 = g_cond[t * 32 + c], cn8 = g_cond[t * 32 + c + 8];
            float acc[3][4];
#pragma unroll
            for (int n = 0; n < 3; n++) { acc[n][0] = b0; acc[n][1] = b0; acc[n][2] = b8; acc[n][3] = b8; }
#pragma unroll
            for (int kc = 0; kc < 8; kc++) {
                int base = ((kc * 2) * 2 + warp) * 32 + lane;
                uint4 Ah = g_wIn[base], Al = g_wIn[base + 64];
#pragma unroll
                for (int n = 0; n < 3; n++) {
                    int coff = (n * 8 + frow) * XT + kc * 16 + fcol;
                    u32 bh0 = *(const u32*)&xT_hi[coff], bh1 = *(const u32*)&xT_hi[coff + 8];
                    u32 bl0 = *(const u32*)&xT_lo[coff], bl1 = *(const u32*)&xT_lo[coff + 8];
                    mma16816(acc[n], Ah, bh0, bh1);
                    mma16816(acc[n], Ah, bl0, bl1);
                    mma16816(acc[n], Al, bh0, bh1);
                }
            }
#pragma unroll
            for (int n = 0; n < 3; n++) {
                int j = n * 8 + fcol;
#pragma unroll
                for (int q = 0; q < 4; q++) fR[n][q] = fmaxf(acc[n][q], 0.f);
                wsplit(hT_hi, hT_lo, (32 + j) * HT + c, fR[n][0] + cn0);
                wsplit(hT_hi, hT_lo, (33 + j) * HT + c, fR[n][1] + cn0);
                wsplit(hT_hi, hT_lo, (32 + j) * HT + c + 8, fR[n][2] + cn8);
                wsplit(hT_hi, hT_lo, (33 + j) * HT + c + 8, fR[n][3] + cn8);
            }
        } else {
#pragma unroll
            for (int n = 0; n < 3; n++) { fR[n][0] = 0.f; fR[n][1] = 0.f; fR[n][2] = 0.f; fR[n][3] = 0.f; }
        }
        __syncthreads();

        for (int l = 0; l < 6; l++) {
            switch (l) {
                case 0: conv_mma<1>(hT_hi, hT_lo, aT_hi, aT_lo, bdil, l, warp, lane); break;
                case 1: conv_mma<2>(hT_hi, hT_lo, aT_hi, aT_lo, bdil, l, warp, lane); break;
                case 2: conv_mma<4>(hT_hi, hT_lo, aT_hi, aT_lo, bdil, l, warp, lane); break;
                case 3: conv_mma<8>(hT_hi, hT_lo, aT_hi, aT_lo, bdil, l, warp, lane); break;
                case 4: conv_mma<16>(hT_hi, hT_lo, aT_hi, aT_lo, bdil, l, warp, lane); break;
                default: conv_mma<32>(hT_hi, hT_lo, aT_hi, aT_lo, bdil, l, warp, lane); break;
            }
            __syncthreads();
            {
                bool resw = (warp < 2);
                if (resw ? (l < 5) : true) {
                    int c = resw ? 16 * warp + frow : 16 * (warp - 2) + frow;
                    int ob = resw ? c : 32 + c;
                    float b0 = bout[l * 64 + ob], b8 = bout[l * 64 + ob + 8];
                    float acc[3][4];
#pragma unroll
                    for (int n = 0; n < 3; n++) { acc[n][0] = b0; acc[n][1] = b0; acc[n][2] = b8; acc[n][3] = b8; }
#pragma unroll
                    for (int kt = 0; kt < 2; kt++) {
                        int base = (((l * 2 + kt) * 2) * 4 + warp) * 32 + lane;
                        uint4 Ah = g_wE[base], Al = g_wE[base + 128];
#pragma unroll
                        for (int n = 0; n < 3; n++) {
                            int coff = (n * 8 + frow) * HT + kt * 16 + fcol;
                            u32 bh0 = *(const u32*)&aT_hi[coff], bh1 = *(const u32*)&aT_hi[coff + 8];
                            u32 bl0 = *(const u32*)&aT_lo[coff], bl1 = *(const u32*)&aT_lo[coff + 8];
                            mma16816(acc[n], Ah, bh0, bh1);
                            mma16816(acc[n], Ah, bl0, bl1);
                            mma16816(acc[n], Al, bh0, bh1);
                        }
                    }
                    if (resw) {
                        float cn0 = g_cond[((l + 1) * NSTEPS + t) * 32 + c];
                        float cn8 = g_cond[((l + 1) * NSTEPS + t) * 32 + c + 8];
#pragma unroll
                        for (int n = 0; n < 3; n++) {
                            int j = n * 8 + fcol;
#pragma unroll
                            for (int q = 0; q < 4; q++)
                                fR[n][q] = (fR[n][q] + acc[n][q]) * 0.70710678118654752f;
                            wsplit(hT_hi, hT_lo, (32 + j) * HT + c, fR[n][0] + cn0);
                            wsplit(hT_hi, hT_lo, (33 + j) * HT + c, fR[n][1] + cn0);
                            wsplit(hT_hi, hT_lo, (32 + j) * HT + c + 8, fR[n][2] + cn8);
                            wsplit(hT_hi, hT_lo, (33 + j) * HT + c + 8, fR[n][3] + cn8);
                        }
                    } else {
#pragma unroll
                        for (int n = 0; n < 3; n++) {
#pragma unroll
                            for (int q = 0; q < 4; q++) fR[n][q] += acc[n][q];
                        }
                        if (l == 5) {
#pragma unroll
                            for (int n = 0; n < 3; n++) {
                                int j = n * 8 + fcol;
                                wsplit(skT_hi, skT_lo, j * HT + c, fR[n][0]);
                                wsplit(skT_hi, skT_lo, (j + 1) * HT + c, fR[n][1]);
                                wsplit(skT_hi, skT_lo, j * HT + c + 8, fR[n][2]);
                                wsplit(skT_hi, skT_lo, (j + 1) * HT + c + 8, fR[n][3]);
                            }
                        }
                    }
                }
            }
            __syncthreads();
        }
        // F: s = relu(W_o1 @ skip/sqrt6 + b) via MMA, warps 0-1 -> sT (in aT)
        if (warp < 2) {
            int c = 16 * warp + frow;
            float b0 = b_o1[c], b8 = b_o1[c + 8];
            float acc[3][4];
#pragma unroll
            for (int n = 0; n < 3; n++) { acc[n][0] = b0; acc[n][1] = b0; acc[n][2] = b8; acc[n][3] = b8; }
#pragma unroll
            for (int kt = 0; kt < 2; kt++) {
                int base = ((kt * 2) * 2 + warp) * 32 + lane;
                uint4 Ah = g_wF[base], Al = g_wF[base + 64];
#pragma unroll
                for (int n = 0; n < 3; n++) {
                    int coff = (n * 8 + frow) * HT + kt * 16 + fcol;
                    u32 bh0 = *(const u32*)&skT_hi[coff], bh1 = *(const u32*)&skT_hi[coff + 8];
                    u32 bl0 = *(const u32*)&skT_lo[coff], bl1 = *(const u32*)&skT_lo[coff + 8];
                    mma16816(acc[n], Ah, bh0, bh1);
                    mma16816(acc[n], Ah, bl0, bl1);
                    mma16816(acc[n], Al, bh0, bh1);
                }
            }
#pragma unroll
            for (int n = 0; n < 3; n++) {
                int j = n * 8 + fcol;
                wsplit(aT_hi, aT_lo, j * HT + c, fmaxf(acc[n][0], 0.f));
                wsplit(aT_hi, aT_lo, (j + 1) * HT + c, fmaxf(acc[n][1], 0.f));
                wsplit(aT_hi, aT_lo, j * HT + c + 8, fmaxf(acc[n][2], 0.f));
                wsplit(aT_hi, aT_lo, (j + 1) * HT + c + 8, fmaxf(acc[n][3], 0.f));
            }
        }
        __syncthreads();
        // G: eps = W_o2 @ s via MMA (all warps, 2 m-tiles each); DDPM update of split-x
#pragma unroll
        for (int m = 0; m < 2; m++) {
            int mt8 = 2 * warp + m, dbase = 16 * mt8;
            float b0 = b_o2[dbase + frow], b8 = b_o2[dbase + frow + 8];
            float acc[3][4];
#pragma unroll
            for (int n = 0; n < 3; n++) { acc[n][0] = b0; acc[n][1] = b0; acc[n][2] = b8; acc[n][3] = b8; }
#pragma unroll
            for (int kt = 0; kt < 2; kt++) {
                int base = ((kt * 2) * 8 + mt8) * 32 + lane;
                uint4 Ah = g_wG[base], Al = g_wG[base + 256];
#pragma unroll
                for (int n = 0; n < 3; n++) {
                    int coff = (n * 8 + frow) * HT + kt * 16 + fcol;
                    u32 bh0 = *(const u32*)&aT_hi[coff], bh1 = *(const u32*)&aT_hi[coff + 8];
                    u32 bl0 = *(const u32*)&aT_lo[coff], bl1 = *(const u32*)&aT_lo[coff + 8];
                    mma16816(acc[n], Ah, bh0, bh1);
                    mma16816(acc[n], Ah, bl0, bl1);
                    mma16816(acc[n], Al, bh0, bh1);
                }
            }
            if (m == 0) asm volatile("cp.async.wait_group 0;" ::: "memory");
#pragma unroll
            for (int n = 0; n < 3; n++)
#pragma unroll
                for (int r = 0; r < 2; r++)
#pragma unroll
                    for (int e = 0; e < 2; e++) {
                        int d = dbase + frow + 8 * r;
                        int j = n * 8 + fcol + e;
                        int xa = j * XT + d;
                        float x = __half2float(xT_hi[xa]) + __half2float(xT_lo[xa]);
                        float nz = nzS[d * 24 + j];
                        float eps = acc[n][2 * r + e];
                        float x0 = fminf(fmaxf((x - s1m * eps) * isab, -1.f), 1.f);
                        float xn = fmaf(c0, x0, fmaf(cxt, x, sg * nz));
                        wsplit(xT_hi, xT_lo, xa, xn);
                    }
        }
        __syncthreads();
    }
    {
        int b = chain & 31;
        float lc = g_loc[b * 128 + tid];
        float scl = g_scale[b * 128 + tid];
        for (int hh = 0; hh < 24; hh++) {
            int xa = hh * XT + tid;
            double z = (double)(__half2float(xT_hi[xa]) + __half2float(xT_lo[xa]));
            double u = 0.5 * erfc(-z * 0.70710678118654752440);
            u = fmin(fmax(u, 1e-6), 1.0 - 1e-6);
            double a = 4.0 * u * (1.0 - u);
            a = fmin(fmax(a, 1e-12), 1.0);
            double r = sqrt(a);
            double q = 2.0 * sqrt(fmax(cos(acos(r) / 3.0) / r - 1.0, 0.0));
            double sgn = (u >= 0.5) ? 1.0 : -1.0;
            out[((size_t)chain * 24 + hh) * 128 + tid] = (float)((double)lc + (double)scl * sgn * q);
        }
    }
}

extern "C" void kernel_launch(void* const* d_in, const int* in_sizes, int n_in,
                              void* d_out, int out_size) {
    const float* x_hist = (const float*)d_in[0];
    const float* z_init = (const float*)d_in[1];
    const float* noise = (const float*)d_in[2];
    const float* w_in = (const float*)d_in[3];
    const float* b_in = (const float*)d_in[4];
    const float* tw1 = (const float*)d_in[5];
    const float* tb1 = (const float*)d_in[6];
    const float* tw2 = (const float*)d_in[7];
    const float* tb2 = (const float*)d_in[8];
    const float* lwt = (const float*)d_in[9];
    const float* lbt = (const float*)d_in[10];
    const float* lwd = (const float*)d_in[11];
    const float* lbd = (const float*)d_in[12];
    const float* lwo = (const float*)d_in[13];
    const float* lbo = (const float*)d_in[14];
    const float* w_o1 = (const float*)d_in[15];
    const float* b_o1 = (const float*)d_in[16];
    const float* w_o2 = (const float*)d_in[17];
    const float* b_o2 = (const float*)d_in[18];
    float* out = (float*)d_out;

    const int SMEM = 47104;
    cudaFuncSetAttribute(k_main, cudaFuncAttributeMaxDynamicSharedMemorySize, SMEM);
    k_prep<<<64, 256>>>(w_in, lwd, lwo, w_o1, w_o2);
    k_stats<<<32, 128>>>(x_hist);
    k_temb<<<50, 512>>>(tw1, tb1, tw2, tb2, lwt, lbt);
    k_main<<<512, 128, SMEM>>>(z_init, noise, b_in, lbd, lbo, b_o1, b_o2, out);
}